// round 3
// baseline (speedup 1.0000x reference)
#include <cuda_runtime.h>

// ContMix fused implementation, fp32.
// B=32, C=64, H=W=56, G=4, C2=32, SMK=5, K=7, SCALE=0.25
//
// Kernel 1: kg[b][oc][l] = bn(wk_w @ avgpool8x8(x[:,32:])) -> (32, 32, 49)
// Kernel 2: one block per (b, h) row of 56 pixels; fully fused attention +
//           mixing + lepe + output projection.

#define NB 32
#define NC 64
#define NH 56
#define NW 56

__device__ float g_kg[NB * 32 * 49];

// Smem layout (floats)
#define O_WQ    0        // 1024
#define O_WQS   1024     // 32
#define O_WQB   1056     // 32
#define O_WP    1088     // 3626
#define O_WPB   4714     // 74
#define O_DYW   4788     // 4096
#define O_DYS   8884     // 64
#define O_DYB   8948     // 64
#define O_LEPW  9012     // 3136
#define O_LSC   12148    // 64
#define O_LOF   12212    // 64
#define O_KG    12276    // 1568
#define O_RPB1  13844    // 324
#define O_RPB2  14168    // 676
#define O_Q     14844    // 1792  q[o*56+p]
#define O_ATTN  16636    // 56*297 = 16632  attn[p*297 + g*74 + m]
#define O_WL    33268    // 10976 union { xrow 1792, wl 10976, m 56*65 }
#define O_LEP   44244    // 56*65 = 3640
#define O_XCH   47884    // 8*7*64 = 3584
#define SMEM_FLOATS 51468
#define SMEM_BYTES (SMEM_FLOATS * 4)

// clamp helper matching numpy repeat-based bias index construction
__device__ __forceinline__ int bcl(int r, int kh, int k) {
    return r < kh ? r : (r >= 56 - kh ? (k - 1) - (55 - r) : kh);
}

__global__ void k_pool(const float* __restrict__ x,
                       const float* __restrict__ wk_w,
                       const float* __restrict__ wk_s,
                       const float* __restrict__ wk_b,
                       float* __restrict__ kg) {
    const int b = blockIdx.x;
    const int tid = threadIdx.x;
    __shared__ float s_pool[32 * 49];
    __shared__ float s_wk[32 * 32];
    for (int t = tid; t < 1024; t += 256) s_wk[t] = wk_w[t];
    for (int t = tid; t < 1568; t += 256) {
        int ic = t / 49, l = t % 49;
        int i = l / 7, j = l % 7;
        const float* base = x + (((size_t)b * NC + 32 + ic) * NH + i * 8) * NW + j * 8;
        float s = 0.f;
        #pragma unroll
        for (int y = 0; y < 8; y++) {
            #pragma unroll
            for (int xx = 0; xx < 8; xx++) s += base[y * NW + xx];
        }
        s_pool[t] = s * (1.0f / 64.0f);
    }
    __syncthreads();
    for (int t = tid; t < 1568; t += 256) {
        int oc = t / 49, l = t % 49;
        float acc = 0.f;
        #pragma unroll
        for (int ic = 0; ic < 32; ic++)
            acc += s_wk[oc * 32 + ic] * s_pool[ic * 49 + l];
        kg[(size_t)b * 1568 + t] = acc * wk_s[oc] + wk_b[oc];
    }
}

__global__ __launch_bounds__(256, 1)
void k_main(const float* __restrict__ x,
            const float* __restrict__ lepe_w, const float* __restrict__ lepe_b,
            const float* __restrict__ lepe_s, const float* __restrict__ lepe_bb,
            const float* __restrict__ wq_w, const float* __restrict__ wq_s,
            const float* __restrict__ wq_b,
            const float* __restrict__ wp_w, const float* __restrict__ wp_b,
            const float* __restrict__ rpb1, const float* __restrict__ rpb2,
            const float* __restrict__ dy_w, const float* __restrict__ dy_s,
            const float* __restrict__ dy_b,
            const float* __restrict__ kg,
            float* __restrict__ out) {
    extern __shared__ float sm[];
    const int h = blockIdx.x;
    const int b = blockIdx.y;
    const int tid = threadIdx.x;

    float* s_wq   = sm + O_WQ;
    float* s_wqs  = sm + O_WQS;
    float* s_wqb  = sm + O_WQB;
    float* s_wp   = sm + O_WP;
    float* s_wpb  = sm + O_WPB;
    float* s_dyw  = sm + O_DYW;
    float* s_dys  = sm + O_DYS;
    float* s_dyb  = sm + O_DYB;
    float* s_lepw = sm + O_LEPW;
    float* s_lsc  = sm + O_LSC;
    float* s_lof  = sm + O_LOF;
    float* s_kg   = sm + O_KG;
    float* s_rpb1 = sm + O_RPB1;
    float* s_rpb2 = sm + O_RPB2;
    float* s_q    = sm + O_Q;
    float* s_attn = sm + O_ATTN;
    float* s_lep  = sm + O_LEP;
    float* s_xch  = sm + O_XCH;

    // ---- P0: stage weights ----
    for (int t = tid; t < 1024; t += 256) s_wq[t] = wq_w[t];
    if (tid < 32) { s_wqs[tid] = wq_s[tid]; s_wqb[tid] = wq_b[tid]; }
    for (int t = tid; t < 3626; t += 256) s_wp[t] = wp_w[t];
    if (tid < 74) s_wpb[tid] = wp_b[tid];
    for (int t = tid; t < 4096; t += 256) s_dyw[t] = dy_w[t];
    if (tid < 64) {
        s_dys[tid] = dy_s[tid];
        s_dyb[tid] = dy_b[tid];
        float s = lepe_s[tid];
        s_lsc[tid] = s;
        s_lof[tid] = lepe_b[tid] * s + lepe_bb[tid];
    }
    for (int t = tid; t < 3136; t += 256) s_lepw[t] = lepe_w[t];
    for (int t = tid; t < 1568; t += 256) s_kg[t] = kg[(size_t)b * 1568 + t];
    for (int t = tid; t < 324; t += 256) s_rpb1[t] = rpb1[t];
    for (int t = tid; t < 676; t += 256) s_rpb2[t] = rpb2[t];

    // xrow: first 32 channels of this row, into the union buffer
    float* s_xrow = sm + O_WL;
    for (int t = tid; t < 1792; t += 256) {
        int i = t / 56, p = t % 56;
        s_xrow[t] = x[(((size_t)b * NC + i) * NH + h) * NW + p];
    }
    __syncthreads();

    // ---- P1: q projection ----
    for (int t = tid; t < 1792; t += 256) {
        int o = t / 56, p = t % 56;
        float acc = 0.f;
        #pragma unroll
        for (int i = 0; i < 32; i++)
            acc += s_wq[o * 32 + i] * s_xrow[i * 56 + p];
        s_q[o * 56 + p] = (acc * s_wqs[o] + s_wqb[o]) * 0.25f;
    }
    __syncthreads();

    // ---- P2: wl[p][g][l] = sum_c q[g*8+c][p] * kg[g*8+c][l] ----
    float* s_wl = sm + O_WL;  // overwrites xrow (done with it)
    for (int t = tid; t < 10976; t += 256) {
        int l = t % 49, g = (t / 49) & 3, p = t / 196;
        float acc = 0.f;
        #pragma unroll
        for (int c2 = 0; c2 < 8; c2++)
            acc += s_q[(g * 8 + c2) * 56 + p] * s_kg[(g * 8 + c2) * 49 + l];
        s_wl[(p * 4 + g) * 49 + l] = acc;
    }
    __syncthreads();

    // ---- P3+P4: wp GEMM (74x49) + rpb + dual softmax, one thread per (p,g)
    if (tid < 224) {
        int p = tid % 56, g = tid / 56;
        const float* wl = s_wl + (p * 4 + g) * 49;
        float acc[74];
        #pragma unroll
        for (int m = 0; m < 74; m++) acc[m] = s_wpb[m];
        for (int l = 0; l < 49; l++) {
            float v = wl[l];
            #pragma unroll
            for (int m = 0; m < 74; m++)
                acc[m] += s_wp[m * 49 + l] * v;
        }
        // relative position bias (derived from numpy _bias_idx incl. [::-1])
        int bh5 = bcl(55 - h, 2, 5), bw5 = bcl(55 - p, 2, 5);
        int bh7 = bcl(55 - h, 3, 7), bw7 = bcl(55 - p, 3, 7);
        const float* r1 = s_rpb1 + g * 81;
        const float* r2 = s_rpb2 + g * 169;
        #pragma unroll
        for (int m = 0; m < 25; m++) {
            int dh = m / 5, dw = m % 5;
            acc[m] += r1[(bh5 + dh) * 9 + bw5 + dw];
        }
        #pragma unroll
        for (int j = 0; j < 49; j++) {
            int dh = j / 7, dw = j % 7;
            acc[25 + j] += r2[(bh7 + dh) * 13 + bw7 + dw];
        }
        float* ap = s_attn + p * 297 + g * 74;
        // softmax over taps [0,25)
        {
            float mx = -1e30f;
            #pragma unroll
            for (int m = 0; m < 25; m++) mx = fmaxf(mx, acc[m]);
            float s = 0.f;
            #pragma unroll
            for (int m = 0; m < 25; m++) { acc[m] = expf(acc[m] - mx); s += acc[m]; }
            float inv = 1.0f / s;
            #pragma unroll
            for (int m = 0; m < 25; m++) ap[m] = acc[m] * inv;
        }
        // softmax over taps [25,74)
        {
            float mx = -1e30f;
            #pragma unroll
            for (int m = 25; m < 74; m++) mx = fmaxf(mx, acc[m]);
            float s = 0.f;
            #pragma unroll
            for (int m = 25; m < 74; m++) { acc[m] = expf(acc[m] - mx); s += acc[m]; }
            float inv = 1.0f / s;
            #pragma unroll
            for (int m = 25; m < 74; m++) ap[m] = acc[m] * inv;
        }
    }
    __syncthreads();

    // ---- P5: fused lepe + dynamic mixing, 8-channel x-tile chunks ----
    float* s_m = sm + O_WL;  // reuse: m[p*65 + ch]
    const int p5 = tid % 56;
    const int grp = tid / 56;  // 0..3 active (tid<224)
    for (int cc = 0; cc < 8; cc++) {
        // stage x[ b, cc*8 .. cc*8+7, h-3..h+3, -3..60 ] (zero padded)
        for (int t = tid; t < 3584; t += 256) {
            int j = t / 448;
            int rem = t % 448;
            int rr = rem / 64, wi = rem % 64;
            int gy = h - 3 + rr, gw = wi - 3;
            float v = 0.f;
            if ((unsigned)gy < 56u && (unsigned)gw < 56u)
                v = x[(((size_t)b * NC + cc * 8 + j) * NH + gy) * NW + gw];
            s_xch[t] = v;
        }
        __syncthreads();
        if (tid < 224) {
            int g = cc & 3;
            const float* at = s_attn + p5 * 297 + g * 74;
            if (cc < 4) {
                float a1[25];
                #pragma unroll
                for (int j = 0; j < 25; j++) a1[j] = at[j];
                #pragma unroll
                for (int c2 = 0; c2 < 2; c2++) {
                    int chl = grp * 2 + c2;
                    int ch = cc * 8 + chl;
                    const float* xb = s_xch + chl * 448;
                    const float* lw = s_lepw + ch * 49;
                    float lac = 0.f, mac = 0.f;
                    #pragma unroll
                    for (int dh = 0; dh < 7; dh++) {
                        #pragma unroll
                        for (int dw = 0; dw < 7; dw++) {
                            float xv = xb[dh * 64 + p5 + dw];
                            lac += lw[dh * 7 + dw] * xv;
                            if (dh >= 1 && dh <= 5 && dw >= 1 && dw <= 5)
                                mac += a1[(dh - 1) * 5 + (dw - 1)] * xv;
                        }
                    }
                    s_m[p5 * 65 + ch] = mac;
                    s_lep[p5 * 65 + ch] = lac * s_lsc[ch] + s_lof[ch];
                }
            } else {
                float a2[49];
                #pragma unroll
                for (int j = 0; j < 49; j++) a2[j] = at[25 + j];
                #pragma unroll
                for (int c2 = 0; c2 < 2; c2++) {
                    int chl = grp * 2 + c2;
                    int ch = cc * 8 + chl;
                    const float* xb = s_xch + chl * 448;
                    const float* lw = s_lepw + ch * 49;
                    float lac = 0.f, mac = 0.f;
                    #pragma unroll
                    for (int dh = 0; dh < 7; dh++) {
                        #pragma unroll
                        for (int dw = 0; dw < 7; dw++) {
                            float xv = xb[dh * 64 + p5 + dw];
                            lac += lw[dh * 7 + dw] * xv;
                            mac += a2[dh * 7 + dw] * xv;
                        }
                    }
                    s_m[p5 * 65 + ch] = mac;
                    s_lep[p5 * 65 + ch] = lac * s_lsc[ch] + s_lof[ch];
                }
            }
        }
        __syncthreads();
    }

    // ---- P6: dy 64x64 GEMM + bn + lepe, 4 outputs per thread-task ----
    for (int t = tid; t < 896; t += 256) {
        int og = t / 56, p = t % 56;
        int o0 = og * 4;
        const float* mm = s_m + p * 65;
        float a0 = 0.f, a1 = 0.f, a2 = 0.f, a3 = 0.f;
        #pragma unroll
        for (int i = 0; i < 64; i++) {
            float mv = mm[i];
            a0 += s_dyw[(o0 + 0) * 64 + i] * mv;
            a1 += s_dyw[(o0 + 1) * 64 + i] * mv;
            a2 += s_dyw[(o0 + 2) * 64 + i] * mv;
            a3 += s_dyw[(o0 + 3) * 64 + i] * mv;
        }
        size_t base = (((size_t)b * NC + o0) * NH + h) * NW + p;
        out[base + 0 * NH * NW] = a0 * s_dys[o0 + 0] + s_dyb[o0 + 0] + s_lep[p * 65 + o0 + 0];
        out[base + 1 * NH * NW] = a1 * s_dys[o0 + 1] + s_dyb[o0 + 1] + s_lep[p * 65 + o0 + 1];
        out[base + 2 * NH * NW] = a2 * s_dys[o0 + 2] + s_dyb[o0 + 2] + s_lep[p * 65 + o0 + 2];
        out[base + 3 * NH * NW] = a3 * s_dys[o0 + 3] + s_dyb[o0 + 3] + s_lep[p * 65 + o0 + 3];
    }
}

extern "C" void kernel_launch(void* const* d_in, const int* in_sizes, int n_in,
                              void* d_out, int out_size) {
    const float* x       = (const float*)d_in[0];
    const float* lepe_w  = (const float*)d_in[1];
    const float* lepe_b  = (const float*)d_in[2];
    const float* lepe_s  = (const float*)d_in[3];
    const float* lepe_bb = (const float*)d_in[4];
    const float* wq_w    = (const float*)d_in[5];
    const float* wq_s    = (const float*)d_in[6];
    const float* wq_b    = (const float*)d_in[7];
    const float* wk_w    = (const float*)d_in[8];
    const float* wk_s    = (const float*)d_in[9];
    const float* wk_b    = (const float*)d_in[10];
    const float* wp_w    = (const float*)d_in[11];
    const float* wp_b    = (const float*)d_in[12];
    const float* rpb1    = (const float*)d_in[13];
    const float* rpb2    = (const float*)d_in[14];
    const float* dy_w    = (const float*)d_in[15];
    const float* dy_s    = (const float*)d_in[16];
    const float* dy_b    = (const float*)d_in[17];
    float* out = (float*)d_out;

    float* kg = nullptr;
    cudaGetSymbolAddress((void**)&kg, g_kg);

    cudaFuncSetAttribute(k_main, cudaFuncAttributeMaxDynamicSharedMemorySize, SMEM_BYTES);

    k_pool<<<NB, 256>>>(x, wk_w, wk_s, wk_b, kg);
    k_main<<<dim3(NH, NB), 256, SMEM_BYTES>>>(
        x, lepe_w, lepe_b, lepe_s, lepe_bb,
        wq_w, wq_s, wq_b, wp_w, wp_b,
        rpb1, rpb2, dy_w, dy_s, dy_b, kg, out);
}

// round 5
// speedup vs baseline: 1.2477x; 1.2477x over previous
#include <cuda_runtime.h>

// ContMix fused implementation, fp32 + packed f32x2 FMA.
// B=32, C=64, H=W=56, G=4, C2=32, SMK=5, K=7, SCALE=0.25

#define NB 32
#define NC 64
#define NH 56
#define NW 56

__device__ float g_kg[NB * 32 * 49];

// Smem layout (float offsets; float4 regions are 16B-aligned: offset%4==0)
#define O_WQ    0        // 1024
#define O_WQS   1024     // 32
#define O_WQB   1056     // 32
#define O_WPT   1088     // 49*76 = 3724 (transposed wp, padded to 76 cols)
#define O_WPB   4812     // 76 (padded)
#define O_DYW   4888     // 4096
#define O_DYS   8984     // 64
#define O_DYB   9048     // 64
#define O_LEPW  9112     // 3136
#define O_LSC   12248    // 64
#define O_LOF   12312    // 64
#define O_KGT   12376    // 49*32 = 1568 (transposed kg)
#define O_RPB1  13944    // 324
#define O_RPB2  14268    // 676
#define O_Q     14944    // 1792  q[o*56+p]
#define O_ATTN  16736    // 56*297 = 16632  attn[p*297 + g*74 + m]
#define O_M     33368    // 56*68 = 3808 (union: xrow 1792 in P0/P1, m in P5/P6)
#define O_LEP   37176    // 56*68 = 3808
#define O_XCH   40984    // 8*7*64 = 3584
#define SMEM_FLOATS 44568
#define SMEM_BYTES (SMEM_FLOATS * 4)

// clamp helper matching numpy repeat-based bias index construction
__device__ __forceinline__ int bcl(int r, int kh, int k) {
    return r < kh ? r : (r >= 56 - kh ? (k - 1) - (55 - r) : kh);
}

__global__ void k_pool(const float* __restrict__ x,
                       const float* __restrict__ wk_w,
                       const float* __restrict__ wk_s,
                       const float* __restrict__ wk_b,
                       float* __restrict__ kg) {
    const int b = blockIdx.x;
    const int tid = threadIdx.x;
    __shared__ float s_pool[32 * 49];
    __shared__ float s_wk[32 * 32];
    for (int t = tid; t < 1024; t += 256) s_wk[t] = wk_w[t];
    for (int t = tid; t < 1568; t += 256) {
        int ic = t / 49, l = t % 49;
        int i = l / 7, j = l % 7;
        const float* base = x + (((size_t)b * NC + 32 + ic) * NH + i * 8) * NW + j * 8;
        float s = 0.f;
        #pragma unroll
        for (int y = 0; y < 8; y++) {
            #pragma unroll
            for (int xx = 0; xx < 8; xx++) s += base[y * NW + xx];
        }
        s_pool[t] = s * (1.0f / 64.0f);
    }
    __syncthreads();
    for (int t = tid; t < 1568; t += 256) {
        int oc = t / 49, l = t % 49;
        float acc = 0.f;
        #pragma unroll
        for (int ic = 0; ic < 32; ic++)
            acc += s_wk[oc * 32 + ic] * s_pool[ic * 49 + l];
        kg[(size_t)b * 1568 + t] = acc * wk_s[oc] + wk_b[oc];
    }
}

__global__ __launch_bounds__(256, 1)
void k_main(const float* __restrict__ x,
            const float* __restrict__ lepe_w, const float* __restrict__ lepe_b,
            const float* __restrict__ lepe_s, const float* __restrict__ lepe_bb,
            const float* __restrict__ wq_w, const float* __restrict__ wq_s,
            const float* __restrict__ wq_b,
            const float* __restrict__ wp_w, const float* __restrict__ wp_b,
            const float* __restrict__ rpb1, const float* __restrict__ rpb2,
            const float* __restrict__ dy_w, const float* __restrict__ dy_s,
            const float* __restrict__ dy_b,
            const float* __restrict__ kg,
            float* __restrict__ out) {
    extern __shared__ float sm[];
    const int h = blockIdx.x;
    const int b = blockIdx.y;
    const int tid = threadIdx.x;

    float* s_wq   = sm + O_WQ;
    float* s_wqs  = sm + O_WQS;
    float* s_wqb  = sm + O_WQB;
    float* s_wpT  = sm + O_WPT;
    float* s_wpb  = sm + O_WPB;
    float* s_dyw  = sm + O_DYW;
    float* s_dys  = sm + O_DYS;
    float* s_dyb  = sm + O_DYB;
    float* s_lepw = sm + O_LEPW;
    float* s_lsc  = sm + O_LSC;
    float* s_lof  = sm + O_LOF;
    float* s_kgT  = sm + O_KGT;
    float* s_rpb1 = sm + O_RPB1;
    float* s_rpb2 = sm + O_RPB2;
    float* s_q    = sm + O_Q;
    float* s_attn = sm + O_ATTN;
    float* s_lep  = sm + O_LEP;
    float* s_xch  = sm + O_XCH;

    // ---- P0: stage weights ----
    for (int t = tid; t < 1024; t += 256) s_wq[t] = wq_w[t];
    if (tid < 32) { s_wqs[tid] = wq_s[tid]; s_wqb[tid] = wq_b[tid]; }
    // transposed wp: s_wpT[l*76 + m] = wp_w[m*49 + l], pad m=74,75 with 0
    for (int t = tid; t < 3626; t += 256) {
        int m = t / 49, l = t % 49;
        s_wpT[l * 76 + m] = wp_w[t];
    }
    if (tid < 98) {
        int l = tid >> 1, j = tid & 1;
        s_wpT[l * 76 + 74 + j] = 0.f;
    }
    if (tid < 76) s_wpb[tid] = (tid < 74) ? wp_b[tid] : 0.f;
    for (int t = tid; t < 4096; t += 256) s_dyw[t] = dy_w[t];
    if (tid < 64) {
        s_dys[tid] = dy_s[tid];
        s_dyb[tid] = dy_b[tid];
        float s = lepe_s[tid];
        s_lsc[tid] = s;
        s_lof[tid] = lepe_b[tid] * s + lepe_bb[tid];
    }
    for (int t = tid; t < 3136; t += 256) s_lepw[t] = lepe_w[t];
    // transposed kg: s_kgT[l*32 + ic] = kg[b][ic][l]  (coalesced read)
    for (int t = tid; t < 1568; t += 256) {
        int ic = t / 49, l = t % 49;
        s_kgT[l * 32 + ic] = kg[(size_t)b * 1568 + t];
    }
    for (int t = tid; t < 324; t += 256) s_rpb1[t] = rpb1[t];
    for (int t = tid; t < 676; t += 256) s_rpb2[t] = rpb2[t];

    // xrow: first 32 channels of this row, into the union buffer (O_M)
    float* s_xrow = sm + O_M;
    for (int t = tid; t < 1792; t += 256) {
        int i = t / 56, p = t % 56;
        s_xrow[t] = x[(((size_t)b * NC + i) * NH + h) * NW + p];
    }
    __syncthreads();

    // ---- P1: q projection ----
    for (int t = tid; t < 1792; t += 256) {
        int o = t / 56, p = t % 56;
        float acc = 0.f;
        #pragma unroll
        for (int i = 0; i < 32; i++)
            acc += s_wq[o * 32 + i] * s_xrow[i * 56 + p];
        s_q[o * 56 + p] = (acc * s_wqs[o] + s_wqb[o]) * 0.25f;
    }
    __syncthreads();

    // ---- P3: fused wl + wp GEMM (f32x2) + rpb + dual softmax ----
    if (tid < 224) {
        const int p = tid % 56, g = tid / 56;
        float qr[8];
        #pragma unroll
        for (int c = 0; c < 8; c++) qr[c] = s_q[(g * 8 + c) * 56 + p];

        unsigned long long acc2[38];
        #pragma unroll
        for (int mm = 0; mm < 38; mm++) {
            float b0 = s_wpb[2 * mm], b1 = s_wpb[2 * mm + 1];
            asm("mov.b64 %0, {%1, %2};" : "=l"(acc2[mm]) : "f"(b0), "f"(b1));
        }
        for (int l = 0; l < 49; l++) {
            const float4 k0 = *(const float4*)(s_kgT + l * 32 + g * 8);
            const float4 k1 = *(const float4*)(s_kgT + l * 32 + g * 8 + 4);
            float v = qr[0] * k0.x + qr[1] * k0.y + qr[2] * k0.z + qr[3] * k0.w
                    + qr[4] * k1.x + qr[5] * k1.y + qr[6] * k1.z + qr[7] * k1.w;
            unsigned long long vv;
            asm("mov.b64 %0, {%1, %1};" : "=l"(vv) : "f"(v));
            const ulonglong2* w2 = (const ulonglong2*)(s_wpT + l * 76);
            #pragma unroll
            for (int mm = 0; mm < 19; mm++) {
                ulonglong2 w = w2[mm];
                asm("fma.rn.f32x2 %0, %1, %2, %0;" : "+l"(acc2[2 * mm])     : "l"(w.x), "l"(vv));
                asm("fma.rn.f32x2 %0, %1, %2, %0;" : "+l"(acc2[2 * mm + 1]) : "l"(w.y), "l"(vv));
            }
        }
        float acc[76];
        #pragma unroll
        for (int mm = 0; mm < 38; mm++)
            asm("mov.b64 {%0, %1}, %2;" : "=f"(acc[2 * mm]), "=f"(acc[2 * mm + 1]) : "l"(acc2[mm]));

        // relative position bias (derived from numpy _bias_idx incl. [::-1])
        int bh5 = bcl(55 - h, 2, 5), bw5 = bcl(55 - p, 2, 5);
        int bh7 = bcl(55 - h, 3, 7), bw7 = bcl(55 - p, 3, 7);
        const float* r1 = s_rpb1 + g * 81;
        const float* r2 = s_rpb2 + g * 169;
        #pragma unroll
        for (int m = 0; m < 25; m++) {
            int dh = m / 5, dw = m % 5;
            acc[m] += r1[(bh5 + dh) * 9 + bw5 + dw];
        }
        #pragma unroll
        for (int j = 0; j < 49; j++) {
            int dh = j / 7, dw = j % 7;
            acc[25 + j] += r2[(bh7 + dh) * 13 + bw7 + dw];
        }
        float* ap = s_attn + p * 297 + g * 74;
        // softmax over taps [0,25)
        {
            float mx = -1e30f;
            #pragma unroll
            for (int m = 0; m < 25; m++) mx = fmaxf(mx, acc[m]);
            float s = 0.f;
            #pragma unroll
            for (int m = 0; m < 25; m++) { acc[m] = __expf(acc[m] - mx); s += acc[m]; }
            float inv = 1.0f / s;
            #pragma unroll
            for (int m = 0; m < 25; m++) ap[m] = acc[m] * inv;
        }
        // softmax over taps [25,74)
        {
            float mx = -1e30f;
            #pragma unroll
            for (int m = 25; m < 74; m++) mx = fmaxf(mx, acc[m]);
            float s = 0.f;
            #pragma unroll
            for (int m = 25; m < 74; m++) { acc[m] = __expf(acc[m] - mx); s += acc[m]; }
            float inv = 1.0f / s;
            #pragma unroll
            for (int m = 25; m < 74; m++) ap[m] = acc[m] * inv;
        }
    }
    __syncthreads();

    // ---- P5: fused lepe + dynamic mixing, 8-channel x-tile chunks ----
    float* s_m = sm + O_M;  // reuse union: m[p*68 + ch]
    const int p5 = tid % 56;
    const int grp = tid / 56;  // 0..3 active (tid<224)
    for (int cc = 0; cc < 8; cc++) {
        // stage x[ b, cc*8 .. cc*8+7, h-3..h+3, -3..60 ] (zero padded)
        for (int t = tid; t < 3584; t += 256) {
            int j = t / 448;
            int rem = t % 448;
            int rr = rem / 64, wi = rem % 64;
            int gy = h - 3 + rr, gw = wi - 3;
            float v = 0.f;
            if ((unsigned)gy < 56u && (unsigned)gw < 56u)
                v = x[(((size_t)b * NC + cc * 8 + j) * NH + gy) * NW + gw];
            s_xch[t] = v;
        }
        __syncthreads();
        if (tid < 224) {
            int g = cc & 3;
            const float* at = s_attn + p5 * 297 + g * 74;
            if (cc < 4) {
                float a1[25];
                #pragma unroll
                for (int j = 0; j < 25; j++) a1[j] = at[j];
                #pragma unroll
                for (int c2 = 0; c2 < 2; c2++) {
                    int chl = grp * 2 + c2;
                    int ch = cc * 8 + chl;
                    const float* xb = s_xch + chl * 448;
                    const float* lw = s_lepw + ch * 49;
                    float lac = 0.f, mac = 0.f;
                    #pragma unroll
                    for (int dh = 0; dh < 7; dh++) {
                        #pragma unroll
                        for (int dw = 0; dw < 7; dw++) {
                            float xv = xb[dh * 64 + p5 + dw];
                            lac += lw[dh * 7 + dw] * xv;
                            if (dh >= 1 && dh <= 5 && dw >= 1 && dw <= 5)
                                mac += a1[(dh - 1) * 5 + (dw - 1)] * xv;
                        }
                    }
                    s_m[p5 * 68 + ch] = mac;
                    s_lep[p5 * 68 + ch] = lac * s_lsc[ch] + s_lof[ch];
                }
            } else {
                float a2[49];
                #pragma unroll
                for (int j = 0; j < 49; j++) a2[j] = at[25 + j];
                #pragma unroll
                for (int c2 = 0; c2 < 2; c2++) {
                    int chl = grp * 2 + c2;
                    int ch = cc * 8 + chl;
                    const float* xb = s_xch + chl * 448;
                    const float* lw = s_lepw + ch * 49;
                    float lac = 0.f, mac = 0.f;
                    #pragma unroll
                    for (int dh = 0; dh < 7; dh++) {
                        #pragma unroll
                        for (int dw = 0; dw < 7; dw++) {
                            float xv = xb[dh * 64 + p5 + dw];
                            lac += lw[dh * 7 + dw] * xv;
                            mac += a2[dh * 7 + dw] * xv;
                        }
                    }
                    s_m[p5 * 68 + ch] = mac;
                    s_lep[p5 * 68 + ch] = lac * s_lsc[ch] + s_lof[ch];
                }
            }
        }
        __syncthreads();
    }

    // ---- P6: dy 64x64 GEMM (float4) + bn + lepe ----
    for (int t = tid; t < 896; t += 256) {
        int og = t / 56, p = t % 56;
        int o0 = og * 4;
        const float4* m4 = (const float4*)(s_m + p * 68);
        const float4* w0 = (const float4*)(s_dyw + (o0 + 0) * 64);
        const float4* w1 = (const float4*)(s_dyw + (o0 + 1) * 64);
        const float4* w2 = (const float4*)(s_dyw + (o0 + 2) * 64);
        const float4* w3 = (const float4*)(s_dyw + (o0 + 3) * 64);
        float a0 = 0.f, a1 = 0.f, a2 = 0.f, a3 = 0.f;
        #pragma unroll
        for (int i = 0; i < 16; i++) {
            float4 mv = m4[i];
            float4 v0 = w0[i], v1 = w1[i], v2 = w2[i], v3 = w3[i];
            a0 += v0.x * mv.x + v0.y * mv.y + v0.z * mv.z + v0.w * mv.w;
            a1 += v1.x * mv.x + v1.y * mv.y + v1.z * mv.z + v1.w * mv.w;
            a2 += v2.x * mv.x + v2.y * mv.y + v2.z * mv.z + v2.w * mv.w;
            a3 += v3.x * mv.x + v3.y * mv.y + v3.z * mv.z + v3.w * mv.w;
        }
        size_t base = (((size_t)b * NC + o0) * NH + h) * NW + p;
        out[base + 0 * NH * NW] = a0 * s_dys[o0 + 0] + s_dyb[o0 + 0] + s_lep[p * 68 + o0 + 0];
        out[base + 1 * NH * NW] = a1 * s_dys[o0 + 1] + s_dyb[o0 + 1] + s_lep[p * 68 + o0 + 1];
        out[base + 2 * NH * NW] = a2 * s_dys[o0 + 2] + s_dyb[o0 + 2] + s_lep[p * 68 + o0 + 2];
        out[base + 3 * NH * NW] = a3 * s_dys[o0 + 3] + s_dyb[o0 + 3] + s_lep[p * 68 + o0 + 3];
    }
}

extern "C" void kernel_launch(void* const* d_in, const int* in_sizes, int n_in,
                              void* d_out, int out_size) {
    const float* x       = (const float*)d_in[0];
    const float* lepe_w  = (const float*)d_in[1];
    const float* lepe_b  = (const float*)d_in[2];
    const float* lepe_s  = (const float*)d_in[3];
    const float* lepe_bb = (const float*)d_in[4];
    const float* wq_w    = (const float*)d_in[5];
    const float* wq_s    = (const float*)d_in[6];
    const float* wq_b    = (const float*)d_in[7];
    const float* wk_w    = (const float*)d_in[8];
    const float* wk_s    = (const float*)d_in[9];
    const float* wk_b    = (const float*)d_in[10];
    const float* wp_w    = (const float*)d_in[11];
    const float* wp_b    = (const float*)d_in[12];
    const float* rpb1    = (const float*)d_in[13];
    const float* rpb2    = (const float*)d_in[14];
    const float* dy_w    = (const float*)d_in[15];
    const float* dy_s    = (const float*)d_in[16];
    const float* dy_b    = (const float*)d_in[17];
    float* out = (float*)d_out;

    float* kg = nullptr;
    cudaGetSymbolAddress((void**)&kg, g_kg);

    cudaFuncSetAttribute(k_main, cudaFuncAttributeMaxDynamicSharedMemorySize, SMEM_BYTES);

    k_pool<<<NB, 256>>>(x, wk_w, wk_s, wk_b, kg);
    k_main<<<dim3(NH, NB), 256, SMEM_BYTES>>>(
        x, lepe_w, lepe_b, lepe_s, lepe_bb,
        wq_w, wq_s, wq_b, wp_w, wp_b,
        rpb1, rpb2, dy_w, dy_s, dy_b, kg, out);
}

// round 6
// speedup vs baseline: 1.6464x; 1.3195x over previous
#include <cuda_runtime.h>

// ContMix fused implementation, fp32 + packed f32x2 FMA, attn-in-registers.
// B=32, C=64, H=W=56, G=4, C2=32, SMK=5, K=7, SCALE=0.25

#define NB 32
#define NC 64
#define NH 56
#define NW 56

__device__ float g_kg[NB * 32 * 49];

// Smem layout (float offsets; float4 regions 16B-aligned)
#define O_WQT   0        // 1024  wqT[i*32+o] (scale-folded)
#define O_QB    1024     // 32    0.25*wq_b
#define O_WPT   1056     // 49*80 = 3920 (transposed wp, padded to 80)
#define O_WPB   4976     // 80 (padded)
#define O_DYW   5056     // 4096
#define O_DYS   9152     // 64
#define O_DYB   9216     // 64
#define O_LEPW  9280     // 3136
#define O_LSC   12416    // 64
#define O_LOF   12480    // 64
#define O_KGT   12544    // 49*32 = 1568 (transposed kg)
#define O_RPB1  14112    // 324
#define O_RPB2  14436    // 676
#define O_M     15112    // 56*68 = 3808 (union: xrow 1792 in P0/P3, m in P5/P6)
#define O_LEP   18920    // 3808
#define O_XCH   22728    // 8*7*64 = 3584
#define SMEM_FLOATS 26312
#define SMEM_BYTES (SMEM_FLOATS * 4)

// clamp helper matching numpy repeat-based bias index construction
__device__ __forceinline__ int bcl(int r, int kh, int k) {
    return r < kh ? r : (r >= 56 - kh ? (k - 1) - (55 - r) : kh);
}

__global__ void k_pool(const float* __restrict__ x,
                       const float* __restrict__ wk_w,
                       const float* __restrict__ wk_s,
                       const float* __restrict__ wk_b,
                       float* __restrict__ kg) {
    const int s = blockIdx.x;      // l-slice 0..6
    const int b = blockIdx.y;
    const int tid = threadIdx.x;
    const int l0 = s * 7;
    __shared__ float s_pool[32 * 7];
    __shared__ float s_wk[32 * 32];
    for (int t = tid; t < 1024; t += 256) s_wk[t] = wk_w[t];
    if (tid < 224) {
        int ic = tid / 7, lj = tid % 7;
        int l = l0 + lj;
        int i = l / 7, j = l % 7;
        const float* base = x + (((size_t)b * NC + 32 + ic) * NH + i * 8) * NW + j * 8;
        float sum = 0.f;
        #pragma unroll
        for (int y = 0; y < 8; y++) {
            #pragma unroll
            for (int xx = 0; xx < 8; xx++) sum += base[y * NW + xx];
        }
        s_pool[ic * 7 + lj] = sum * (1.0f / 64.0f);
    }
    __syncthreads();
    if (tid < 224) {
        int oc = tid / 7, lj = tid % 7;
        float acc = 0.f;
        #pragma unroll
        for (int ic = 0; ic < 32; ic++)
            acc += s_wk[oc * 32 + ic] * s_pool[ic * 7 + lj];
        kg[(size_t)b * 1568 + oc * 49 + l0 + lj] = acc * wk_s[oc] + wk_b[oc];
    }
}

__global__ __launch_bounds__(256, 2)
void k_main(const float* __restrict__ x,
            const float* __restrict__ lepe_w, const float* __restrict__ lepe_b,
            const float* __restrict__ lepe_s, const float* __restrict__ lepe_bb,
            const float* __restrict__ wq_w, const float* __restrict__ wq_s,
            const float* __restrict__ wq_b,
            const float* __restrict__ wp_w, const float* __restrict__ wp_b,
            const float* __restrict__ rpb1, const float* __restrict__ rpb2,
            const float* __restrict__ dy_w, const float* __restrict__ dy_s,
            const float* __restrict__ dy_b,
            const float* __restrict__ kg,
            float* __restrict__ out) {
    extern __shared__ float sm[];
    const int h = blockIdx.x;
    const int b = blockIdx.y;
    const int tid = threadIdx.x;

    float* s_wqT  = sm + O_WQT;
    float* s_qb   = sm + O_QB;
    float* s_wpT  = sm + O_WPT;
    float* s_wpb  = sm + O_WPB;
    float* s_dyw  = sm + O_DYW;
    float* s_dys  = sm + O_DYS;
    float* s_dyb  = sm + O_DYB;
    float* s_lepw = sm + O_LEPW;
    float* s_lsc  = sm + O_LSC;
    float* s_lof  = sm + O_LOF;
    float* s_kgT  = sm + O_KGT;
    float* s_rpb1 = sm + O_RPB1;
    float* s_rpb2 = sm + O_RPB2;
    float* s_lep  = sm + O_LEP;
    float* s_xch  = sm + O_XCH;

    // ---- P0: stage weights ----
    // wqT[i*32+o] = wq_w[o*32+i] * 0.25*wq_s[o]
    for (int t = tid; t < 1024; t += 256) {
        int i = t >> 5, o = t & 31;
        s_wqT[t] = wq_w[o * 32 + i] * 0.25f * wq_s[o];
    }
    if (tid < 32) s_qb[tid] = 0.25f * wq_b[tid];
    // transposed wp: s_wpT[l*80 + m] = wp_w[m*49 + l], pad m=74..79 with 0
    for (int t = tid; t < 3626; t += 256) {
        int m = t / 49, l = t % 49;
        s_wpT[l * 80 + m] = wp_w[t];
    }
    for (int t = tid; t < 294; t += 256) {
        int l = t / 6, j = t % 6;
        s_wpT[l * 80 + 74 + j] = 0.f;
    }
    if (tid < 80) s_wpb[tid] = (tid < 74) ? wp_b[tid] : 0.f;
    for (int t = tid; t < 4096; t += 256) s_dyw[t] = dy_w[t];
    if (tid < 64) {
        s_dys[tid] = dy_s[tid];
        s_dyb[tid] = dy_b[tid];
        float s = lepe_s[tid];
        s_lsc[tid] = s;
        s_lof[tid] = lepe_b[tid] * s + lepe_bb[tid];
    }
    for (int t = tid; t < 3136; t += 256) s_lepw[t] = lepe_w[t];
    // transposed kg: s_kgT[l*32 + ic] = kg[b][ic][l]
    for (int t = tid; t < 1568; t += 256) {
        int ic = t / 49, l = t % 49;
        s_kgT[l * 32 + ic] = kg[(size_t)b * 1568 + t];
    }
    for (int t = tid; t < 324; t += 256) s_rpb1[t] = rpb1[t];
    for (int t = tid; t < 676; t += 256) s_rpb2[t] = rpb2[t];

    // xrow: first 32 channels of this row, into the union buffer (O_M)
    float* s_xrow = sm + O_M;
    for (int t = tid; t < 1792; t += 256) {
        int i = t / 56, p = t % 56;
        s_xrow[t] = x[(((size_t)b * NC + i) * NH + h) * NW + p];
    }
    __syncthreads();

    const int p = tid % 56;
    const int g = tid / 56;   // valid when tid < 224

    // ---- P3: q-proj (regs) + fused wl/wp GEMM (f32x2, 2 passes) + rpb + softmax;
    //      attn stays in registers through P5 ----
    float attn[74];
    if (tid < 224) {
        float qr[8];
        #pragma unroll
        for (int c = 0; c < 8; c++) qr[c] = s_qb[g * 8 + c];
        #pragma unroll
        for (int i = 0; i < 32; i++) {
            float xv = s_xrow[i * 56 + p];
            const float4* w = (const float4*)(s_wqT + i * 32 + g * 8);
            float4 w0 = w[0], w1 = w[1];
            qr[0] += w0.x * xv; qr[1] += w0.y * xv; qr[2] += w0.z * xv; qr[3] += w0.w * xv;
            qr[4] += w1.x * xv; qr[5] += w1.y * xv; qr[6] += w1.z * xv; qr[7] += w1.w * xv;
        }

        #pragma unroll
        for (int half = 0; half < 2; half++) {
            const int M0 = half * 40;
            unsigned long long acc2[20];
            #pragma unroll
            for (int mm = 0; mm < 20; mm++) {
                float b0 = s_wpb[M0 + 2 * mm], b1 = s_wpb[M0 + 2 * mm + 1];
                asm("mov.b64 %0, {%1, %2};" : "=l"(acc2[mm]) : "f"(b0), "f"(b1));
            }
            for (int l = 0; l < 49; l++) {
                const float4 k0 = *(const float4*)(s_kgT + l * 32 + g * 8);
                const float4 k1 = *(const float4*)(s_kgT + l * 32 + g * 8 + 4);
                float v = qr[0] * k0.x + qr[1] * k0.y + qr[2] * k0.z + qr[3] * k0.w
                        + qr[4] * k1.x + qr[5] * k1.y + qr[6] * k1.z + qr[7] * k1.w;
                unsigned long long vv;
                asm("mov.b64 %0, {%1, %1};" : "=l"(vv) : "f"(v));
                const ulonglong2* w2 = (const ulonglong2*)(s_wpT + l * 80 + M0);
                #pragma unroll
                for (int mm = 0; mm < 10; mm++) {
                    ulonglong2 w = w2[mm];
                    asm("fma.rn.f32x2 %0, %1, %2, %0;" : "+l"(acc2[2 * mm])     : "l"(w.x), "l"(vv));
                    asm("fma.rn.f32x2 %0, %1, %2, %0;" : "+l"(acc2[2 * mm + 1]) : "l"(w.y), "l"(vv));
                }
            }
            #pragma unroll
            for (int mm = 0; mm < 20; mm++) {
                float f0, f1;
                asm("mov.b64 {%0, %1}, %2;" : "=f"(f0), "=f"(f1) : "l"(acc2[mm]));
                int idx = M0 + 2 * mm;
                if (idx < 74)     attn[idx] = f0;
                if (idx + 1 < 74) attn[idx + 1] = f1;
            }
        }

        // relative position bias (derived from numpy _bias_idx incl. [::-1])
        int bh5 = bcl(55 - h, 2, 5), bw5 = bcl(55 - p, 2, 5);
        int bh7 = bcl(55 - h, 3, 7), bw7 = bcl(55 - p, 3, 7);
        const float* r1 = s_rpb1 + g * 81;
        const float* r2 = s_rpb2 + g * 169;
        #pragma unroll
        for (int m = 0; m < 25; m++) {
            int dh = m / 5, dw = m % 5;
            attn[m] += r1[(bh5 + dh) * 9 + bw5 + dw];
        }
        #pragma unroll
        for (int j = 0; j < 49; j++) {
            int dh = j / 7, dw = j % 7;
            attn[25 + j] += r2[(bh7 + dh) * 13 + bw7 + dw];
        }
        // softmax over taps [0,25)
        {
            float mx = -1e30f;
            #pragma unroll
            for (int m = 0; m < 25; m++) mx = fmaxf(mx, attn[m]);
            float s = 0.f;
            #pragma unroll
            for (int m = 0; m < 25; m++) { attn[m] = __expf(attn[m] - mx); s += attn[m]; }
            float inv = 1.0f / s;
            #pragma unroll
            for (int m = 0; m < 25; m++) attn[m] *= inv;
        }
        // softmax over taps [25,74)
        {
            float mx = -1e30f;
            #pragma unroll
            for (int m = 25; m < 74; m++) mx = fmaxf(mx, attn[m]);
            float s = 0.f;
            #pragma unroll
            for (int m = 25; m < 74; m++) { attn[m] = __expf(attn[m] - mx); s += attn[m]; }
            float inv = 1.0f / s;
            #pragma unroll
            for (int m = 25; m < 74; m++) attn[m] *= inv;
        }
    }

    // ---- P5: fused lepe + dynamic mixing; thread (p,g) owns group-g channels.
    // Chunk cc stages 8 channels: slot<4 -> g'*8+cc (half 0), slot>=4 -> 32+g'*8+cc.
    // First write to s_m happens after the first staging barrier, which also
    // guarantees every thread finished reading s_xrow (same union buffer).
    float* s_m = sm + O_M;
    for (int cc = 0; cc < 8; cc++) {
        for (int t = tid; t < 3584; t += 256) {
            int slot = t / 448;
            int rem = t % 448;
            int rr = rem / 64, wi = rem % 64;
            int ch = (slot < 4) ? (slot * 8 + cc) : (32 + (slot - 4) * 8 + cc);
            int gy = h - 3 + rr, gw = wi - 3;
            float v = 0.f;
            if ((unsigned)gy < 56u && (unsigned)gw < 56u)
                v = x[(((size_t)b * NC + ch) * NH + gy) * NW + gw];
            s_xch[t] = v;
        }
        __syncthreads();
        if (tid < 224) {
            const int ch1 = g * 8 + cc;
            const int ch2 = 32 + g * 8 + cc;
            const float* xb1 = s_xch + g * 448;
            const float* xb2 = s_xch + (4 + g) * 448;
            const float* lw1 = s_lepw + ch1 * 49;
            const float* lw2 = s_lepw + ch2 * 49;
            float lac1 = 0.f, mac1 = 0.f, lac2 = 0.f, mac2 = 0.f;
            #pragma unroll
            for (int dh = 0; dh < 7; dh++) {
                #pragma unroll
                for (int dw = 0; dw < 7; dw++) {
                    float xv1 = xb1[dh * 64 + p + dw];
                    float xv2 = xb2[dh * 64 + p + dw];
                    lac1 += lw1[dh * 7 + dw] * xv1;
                    lac2 += lw2[dh * 7 + dw] * xv2;
                    if (dh >= 1 && dh <= 5 && dw >= 1 && dw <= 5)
                        mac1 += attn[(dh - 1) * 5 + (dw - 1)] * xv1;
                    mac2 += attn[25 + dh * 7 + dw] * xv2;
                }
            }
            s_m[p * 68 + ch1] = mac1;
            s_m[p * 68 + ch2] = mac2;
            s_lep[p * 68 + ch1] = lac1 * s_lsc[ch1] + s_lof[ch1];
            s_lep[p * 68 + ch2] = lac2 * s_lsc[ch2] + s_lof[ch2];
        }
        __syncthreads();
    }

    // ---- P6: dy 64x64 GEMM (float4) + bn + lepe ----
    for (int t = tid; t < 896; t += 256) {
        int og = t / 56, pp = t % 56;
        int o0 = og * 4;
        const float4* m4 = (const float4*)(s_m + pp * 68);
        const float4* w0 = (const float4*)(s_dyw + (o0 + 0) * 64);
        const float4* w1 = (const float4*)(s_dyw + (o0 + 1) * 64);
        const float4* w2 = (const float4*)(s_dyw + (o0 + 2) * 64);
        const float4* w3 = (const float4*)(s_dyw + (o0 + 3) * 64);
        float a0 = 0.f, a1 = 0.f, a2 = 0.f, a3 = 0.f;
        #pragma unroll
        for (int i = 0; i < 16; i++) {
            float4 mv = m4[i];
            float4 v0 = w0[i], v1 = w1[i], v2 = w2[i], v3 = w3[i];
            a0 += v0.x * mv.x + v0.y * mv.y + v0.z * mv.z + v0.w * mv.w;
            a1 += v1.x * mv.x + v1.y * mv.y + v1.z * mv.z + v1.w * mv.w;
            a2 += v2.x * mv.x + v2.y * mv.y + v2.z * mv.z + v2.w * mv.w;
            a3 += v3.x * mv.x + v3.y * mv.y + v3.z * mv.z + v3.w * mv.w;
        }
        size_t base = (((size_t)b * NC + o0) * NH + h) * NW + pp;
        out[base + 0 * NH * NW] = a0 * s_dys[o0 + 0] + s_dyb[o0 + 0] + s_lep[pp * 68 + o0 + 0];
        out[base + 1 * NH * NW] = a1 * s_dys[o0 + 1] + s_dyb[o0 + 1] + s_lep[pp * 68 + o0 + 1];
        out[base + 2 * NH * NW] = a2 * s_dys[o0 + 2] + s_dyb[o0 + 2] + s_lep[pp * 68 + o0 + 2];
        out[base + 3 * NH * NW] = a3 * s_dys[o0 + 3] + s_dyb[o0 + 3] + s_lep[pp * 68 + o0 + 3];
    }
}

extern "C" void kernel_launch(void* const* d_in, const int* in_sizes, int n_in,
                              void* d_out, int out_size) {
    const float* x       = (const float*)d_in[0];
    const float* lepe_w  = (const float*)d_in[1];
    const float* lepe_b  = (const float*)d_in[2];
    const float* lepe_s  = (const float*)d_in[3];
    const float* lepe_bb = (const float*)d_in[4];
    const float* wq_w    = (const float*)d_in[5];
    const float* wq_s    = (const float*)d_in[6];
    const float* wq_b    = (const float*)d_in[7];
    const float* wk_w    = (const float*)d_in[8];
    const float* wk_s    = (const float*)d_in[9];
    const float* wk_b    = (const float*)d_in[10];
    const float* wp_w    = (const float*)d_in[11];
    const float* wp_b    = (const float*)d_in[12];
    const float* rpb1    = (const float*)d_in[13];
    const float* rpb2    = (const float*)d_in[14];
    const float* dy_w    = (const float*)d_in[15];
    const float* dy_s    = (const float*)d_in[16];
    const float* dy_b    = (const float*)d_in[17];
    float* out = (float*)d_out;

    float* kgp = nullptr;
    cudaGetSymbolAddress((void**)&kgp, g_kg);

    cudaFuncSetAttribute(k_main, cudaFuncAttributeMaxDynamicSharedMemorySize, SMEM_BYTES);

    k_pool<<<dim3(7, NB), 256>>>(x, wk_w, wk_s, wk_b, kgp);
    k_main<<<dim3(NH, NB), 256, SMEM_BYTES>>>(
        x, lepe_w, lepe_b, lepe_s, lepe_bb,
        wq_w, wq_s, wq_b, wp_w, wp_b,
        rpb1, rpb2, dy_w, dy_s, dy_b, kgp, out);
}

// round 7
// speedup vs baseline: 2.1347x; 1.2966x over previous
#include <cuda_runtime.h>

// ContMix fused implementation, fp32 + packed f32x2 FMA, attn-in-registers,
// pipelined P5 (double-buffered 4-channel sub-chunks).
// B=32, C=64, H=W=56, G=4, C2=32, SMK=5, K=7, SCALE=0.25

#define NB 32
#define NC 64
#define NH 56
#define NW 56

__device__ float g_kg[NB * 32 * 49];

// Smem layout (float offsets; float4 regions 16B-aligned)
#define O_WQT   0        // 1024  wqT[i*32+o] (scale-folded)
#define O_QB    1024     // 32    0.25*wq_b
#define O_WPT   1056     // 49*80 = 3920 (transposed wp, padded to 80)
#define O_WPB   4976     // 80 (padded)
#define O_DYW   5056     // 4096
#define O_DYS   9152     // 64
#define O_DYB   9216     // 64
#define O_LEPW  9280     // 3136
#define O_LSC   12416    // 64
#define O_LOF   12480    // 64
#define O_KGT   12544    // 49*32 = 1568 (transposed kg)
#define O_RPB1  14112    // 324
#define O_RPB2  14436    // 676
#define O_M     15112    // 56*68 = 3808 (union: xrow 1792 in P0/P3, m in P5/P6)
#define O_LEP   18920    // 3808
#define O_XCH   22728    // 2 buffers x 1792 = 3584
#define SMEM_FLOATS 26312
#define SMEM_BYTES (SMEM_FLOATS * 4)

// clamp helper matching numpy repeat-based bias index construction
__device__ __forceinline__ int bcl(int r, int kh, int k) {
    return r < kh ? r : (r >= 56 - kh ? (k - 1) - (55 - r) : kh);
}

__global__ void k_pool(const float* __restrict__ x,
                       const float* __restrict__ wk_w,
                       const float* __restrict__ wk_s,
                       const float* __restrict__ wk_b,
                       float* __restrict__ kg) {
    const int s = blockIdx.x;      // l-slice 0..6
    const int b = blockIdx.y;
    const int tid = threadIdx.x;
    const int l0 = s * 7;
    __shared__ float s_pool[32 * 7];
    __shared__ float s_wk[32 * 32];
    for (int t = tid; t < 1024; t += 256) s_wk[t] = wk_w[t];
    if (tid < 224) {
        int ic = tid / 7, lj = tid % 7;
        int l = l0 + lj;
        int i = l / 7, j = l % 7;
        const float* base = x + (((size_t)b * NC + 32 + ic) * NH + i * 8) * NW + j * 8;
        float sum = 0.f;
        #pragma unroll
        for (int y = 0; y < 8; y++) {
            #pragma unroll
            for (int xx = 0; xx < 8; xx++) sum += base[y * NW + xx];
        }
        s_pool[ic * 7 + lj] = sum * (1.0f / 64.0f);
    }
    __syncthreads();
    if (tid < 224) {
        int oc = tid / 7, lj = tid % 7;
        float acc = 0.f;
        #pragma unroll
        for (int ic = 0; ic < 32; ic++)
            acc += s_wk[oc * 32 + ic] * s_pool[ic * 7 + lj];
        kg[(size_t)b * 1568 + oc * 49 + l0 + lj] = acc * wk_s[oc] + wk_b[oc];
    }
}

__global__ __launch_bounds__(256, 2)
void k_main(const float* __restrict__ x,
            const float* __restrict__ lepe_w, const float* __restrict__ lepe_b,
            const float* __restrict__ lepe_s, const float* __restrict__ lepe_bb,
            const float* __restrict__ wq_w, const float* __restrict__ wq_s,
            const float* __restrict__ wq_b,
            const float* __restrict__ wp_w, const float* __restrict__ wp_b,
            const float* __restrict__ rpb1, const float* __restrict__ rpb2,
            const float* __restrict__ dy_w, const float* __restrict__ dy_s,
            const float* __restrict__ dy_b,
            const float* __restrict__ kg,
            float* __restrict__ out) {
    extern __shared__ float sm[];
    const int h = blockIdx.x;
    const int b = blockIdx.y;
    const int tid = threadIdx.x;

    float* s_wqT  = sm + O_WQT;
    float* s_qb   = sm + O_QB;
    float* s_wpT  = sm + O_WPT;
    float* s_wpb  = sm + O_WPB;
    float* s_dyw  = sm + O_DYW;
    float* s_dys  = sm + O_DYS;
    float* s_dyb  = sm + O_DYB;
    float* s_lepw = sm + O_LEPW;
    float* s_lsc  = sm + O_LSC;
    float* s_lof  = sm + O_LOF;
    float* s_kgT  = sm + O_KGT;
    float* s_rpb1 = sm + O_RPB1;
    float* s_rpb2 = sm + O_RPB2;
    float* s_lep  = sm + O_LEP;

    // ---- P0: stage weights ----
    for (int t = tid; t < 1024; t += 256) {
        int i = t >> 5, o = t & 31;
        s_wqT[t] = wq_w[o * 32 + i] * 0.25f * wq_s[o];
    }
    if (tid < 32) s_qb[tid] = 0.25f * wq_b[tid];
    for (int t = tid; t < 3626; t += 256) {
        int m = t / 49, l = t % 49;
        s_wpT[l * 80 + m] = wp_w[t];
    }
    for (int t = tid; t < 294; t += 256) {
        int l = t / 6, j = t % 6;
        s_wpT[l * 80 + 74 + j] = 0.f;
    }
    if (tid < 80) s_wpb[tid] = (tid < 74) ? wp_b[tid] : 0.f;
    for (int t = tid; t < 4096; t += 256) s_dyw[t] = dy_w[t];
    if (tid < 64) {
        s_dys[tid] = dy_s[tid];
        s_dyb[tid] = dy_b[tid];
        float s = lepe_s[tid];
        s_lsc[tid] = s;
        s_lof[tid] = lepe_b[tid] * s + lepe_bb[tid];
    }
    for (int t = tid; t < 3136; t += 256) s_lepw[t] = lepe_w[t];
    for (int t = tid; t < 1568; t += 256) {
        int ic = t / 49, l = t % 49;
        s_kgT[l * 32 + ic] = kg[(size_t)b * 1568 + t];
    }
    for (int t = tid; t < 324; t += 256) s_rpb1[t] = rpb1[t];
    for (int t = tid; t < 676; t += 256) s_rpb2[t] = rpb2[t];

    // xrow: first 32 channels of this row, into the union buffer (O_M)
    float* s_xrow = sm + O_M;
    for (int t = tid; t < 1792; t += 256) {
        int i = t / 56, p = t % 56;
        s_xrow[t] = x[(((size_t)b * NC + i) * NH + h) * NW + p];
    }
    __syncthreads();

    const int p = tid % 56;
    const int g = tid / 56;   // valid when tid < 224

    // ---- P3: q-proj (regs) + fused wl/wp GEMM (f32x2, 2 passes) + rpb + softmax;
    //      attn stays in registers through P5 ----
    float attn[74];
    if (tid < 224) {
        float qr[8];
        #pragma unroll
        for (int c = 0; c < 8; c++) qr[c] = s_qb[g * 8 + c];
        #pragma unroll
        for (int i = 0; i < 32; i++) {
            float xv = s_xrow[i * 56 + p];
            const float4* w = (const float4*)(s_wqT + i * 32 + g * 8);
            float4 w0 = w[0], w1 = w[1];
            qr[0] += w0.x * xv; qr[1] += w0.y * xv; qr[2] += w0.z * xv; qr[3] += w0.w * xv;
            qr[4] += w1.x * xv; qr[5] += w1.y * xv; qr[6] += w1.z * xv; qr[7] += w1.w * xv;
        }

        #pragma unroll
        for (int half = 0; half < 2; half++) {
            const int M0 = half * 40;
            unsigned long long acc2[20];
            #pragma unroll
            for (int mm = 0; mm < 20; mm++) {
                float b0 = s_wpb[M0 + 2 * mm], b1 = s_wpb[M0 + 2 * mm + 1];
                asm("mov.b64 %0, {%1, %2};" : "=l"(acc2[mm]) : "f"(b0), "f"(b1));
            }
            for (int l = 0; l < 49; l++) {
                const float4 k0 = *(const float4*)(s_kgT + l * 32 + g * 8);
                const float4 k1 = *(const float4*)(s_kgT + l * 32 + g * 8 + 4);
                float v = qr[0] * k0.x + qr[1] * k0.y + qr[2] * k0.z + qr[3] * k0.w
                        + qr[4] * k1.x + qr[5] * k1.y + qr[6] * k1.z + qr[7] * k1.w;
                unsigned long long vv;
                asm("mov.b64 %0, {%1, %1};" : "=l"(vv) : "f"(v));
                const ulonglong2* w2 = (const ulonglong2*)(s_wpT + l * 80 + M0);
                #pragma unroll
                for (int mm = 0; mm < 10; mm++) {
                    ulonglong2 w = w2[mm];
                    asm("fma.rn.f32x2 %0, %1, %2, %0;" : "+l"(acc2[2 * mm])     : "l"(w.x), "l"(vv));
                    asm("fma.rn.f32x2 %0, %1, %2, %0;" : "+l"(acc2[2 * mm + 1]) : "l"(w.y), "l"(vv));
                }
            }
            #pragma unroll
            for (int mm = 0; mm < 20; mm++) {
                float f0, f1;
                asm("mov.b64 {%0, %1}, %2;" : "=f"(f0), "=f"(f1) : "l"(acc2[mm]));
                int idx = M0 + 2 * mm;
                if (idx < 74)     attn[idx] = f0;
                if (idx + 1 < 74) attn[idx + 1] = f1;
            }
        }

        // relative position bias (derived from numpy _bias_idx incl. [::-1])
        int bh5 = bcl(55 - h, 2, 5), bw5 = bcl(55 - p, 2, 5);
        int bh7 = bcl(55 - h, 3, 7), bw7 = bcl(55 - p, 3, 7);
        const float* r1 = s_rpb1 + g * 81;
        const float* r2 = s_rpb2 + g * 169;
        #pragma unroll
        for (int m = 0; m < 25; m++) {
            int dh = m / 5, dw = m % 5;
            attn[m] += r1[(bh5 + dh) * 9 + bw5 + dw];
        }
        #pragma unroll
        for (int j = 0; j < 49; j++) {
            int dh = j / 7, dw = j % 7;
            attn[25 + j] += r2[(bh7 + dh) * 13 + bw7 + dw];
        }
        // softmax over taps [0,25)
        {
            float mx = -1e30f;
            #pragma unroll
            for (int m = 0; m < 25; m++) mx = fmaxf(mx, attn[m]);
            float s = 0.f;
            #pragma unroll
            for (int m = 0; m < 25; m++) { attn[m] = __expf(attn[m] - mx); s += attn[m]; }
            float inv = 1.0f / s;
            #pragma unroll
            for (int m = 0; m < 25; m++) attn[m] *= inv;
        }
        // softmax over taps [25,74)
        {
            float mx = -1e30f;
            #pragma unroll
            for (int m = 25; m < 74; m++) mx = fmaxf(mx, attn[m]);
            float s = 0.f;
            #pragma unroll
            for (int m = 25; m < 74; m++) { attn[m] = __expf(attn[m] - mx); s += attn[m]; }
            float inv = 1.0f / s;
            #pragma unroll
            for (int m = 25; m < 74; m++) attn[m] *= inv;
        }
    }

    // ---- P5: pipelined lepe + dynamic mixing; 16 sub-chunks of 4 channels,
    // double-buffered in xch (2 x 1792 floats). Staging map is division-free:
    // slot = tid>>6 (group), wi = tid&63 (padded column), rr = 0..6 (rows).
    // Sub-chunk sc: half = sc>>3, ccc = sc&7; channels = half*32 + slot*8 + ccc.
    float* s_m = sm + O_M;
    const int slot = tid >> 6;
    const int wi = tid & 63;
    const bool vw = (wi >= 3) && (wi <= 58);
    const int gw = wi - 3;

    // prologue: stage sub-chunk 0 into buffer 0
    {
        const float* src = x + ((size_t)b * NC + slot * 8) * (NH * NW);
        float* dst = sm + O_XCH + slot * 448 + wi;
        #pragma unroll
        for (int rr = 0; rr < 7; rr++) {
            int gy = h - 3 + rr;
            float v = (vw && (unsigned)gy < 56u) ? src[gy * NW + gw] : 0.f;
            dst[rr * 64] = v;
        }
    }
    __syncthreads();   // also guarantees all P3 xrow reads done before s_m writes

    for (int sc = 0; sc < 16; sc++) {
        float nx[7];
        if (sc < 15) {
            int s1 = sc + 1;
            int ch = ((s1 >> 3) << 5) + slot * 8 + (s1 & 7);
            const float* src = x + ((size_t)b * NC + ch) * (NH * NW);
            #pragma unroll
            for (int rr = 0; rr < 7; rr++) {
                int gy = h - 3 + rr;
                nx[rr] = (vw && (unsigned)gy < 56u) ? src[gy * NW + gw] : 0.f;
            }
        }
        if (tid < 224) {
            const float* xb = sm + O_XCH + (sc & 1) * 1792 + g * 448 + p;
            int ccc = sc & 7;
            if (sc < 8) {
                int ch = g * 8 + ccc;
                const float* lw = s_lepw + ch * 49;
                float lac = 0.f, mac = 0.f;
                #pragma unroll
                for (int dh = 0; dh < 7; dh++) {
                    #pragma unroll
                    for (int dw = 0; dw < 7; dw++) {
                        float xv = xb[dh * 64 + dw];
                        lac += lw[dh * 7 + dw] * xv;
                        if (dh >= 1 && dh <= 5 && dw >= 1 && dw <= 5)
                            mac += attn[(dh - 1) * 5 + (dw - 1)] * xv;
                    }
                }
                s_m[p * 68 + ch] = mac;
                s_lep[p * 68 + ch] = lac * s_lsc[ch] + s_lof[ch];
            } else {
                int ch = 32 + g * 8 + ccc;
                const float* lw = s_lepw + ch * 49;
                float lac = 0.f, mac = 0.f;
                #pragma unroll
                for (int dh = 0; dh < 7; dh++) {
                    #pragma unroll
                    for (int dw = 0; dw < 7; dw++) {
                        float xv = xb[dh * 64 + dw];
                        lac += lw[dh * 7 + dw] * xv;
                        mac += attn[25 + dh * 7 + dw] * xv;
                    }
                }
                s_m[p * 68 + ch] = mac;
                s_lep[p * 68 + ch] = lac * s_lsc[ch] + s_lof[ch];
            }
        }
        if (sc < 15) {
            float* dst = sm + O_XCH + ((sc + 1) & 1) * 1792 + slot * 448 + wi;
            #pragma unroll
            for (int rr = 0; rr < 7; rr++) dst[rr * 64] = nx[rr];
        }
        __syncthreads();
    }

    // ---- P6: dy 64x64 GEMM (float4) + bn + lepe ----
    for (int t = tid; t < 896; t += 256) {
        int og = t / 56, pp = t % 56;
        int o0 = og * 4;
        const float4* m4 = (const float4*)(s_m + pp * 68);
        const float4* w0 = (const float4*)(s_dyw + (o0 + 0) * 64);
        const float4* w1 = (const float4*)(s_dyw + (o0 + 1) * 64);
        const float4* w2 = (const float4*)(s_dyw + (o0 + 2) * 64);
        const float4* w3 = (const float4*)(s_dyw + (o0 + 3) * 64);
        float a0 = 0.f, a1 = 0.f, a2 = 0.f, a3 = 0.f;
        #pragma unroll
        for (int i = 0; i < 16; i++) {
            float4 mv = m4[i];
            float4 v0 = w0[i], v1 = w1[i], v2 = w2[i], v3 = w3[i];
            a0 += v0.x * mv.x + v0.y * mv.y + v0.z * mv.z + v0.w * mv.w;
            a1 += v1.x * mv.x + v1.y * mv.y + v1.z * mv.z + v1.w * mv.w;
            a2 += v2.x * mv.x + v2.y * mv.y + v2.z * mv.z + v2.w * mv.w;
            a3 += v3.x * mv.x + v3.y * mv.y + v3.z * mv.z + v3.w * mv.w;
        }
        size_t base = (((size_t)b * NC + o0) * NH + h) * NW + pp;
        out[base + 0 * NH * NW] = a0 * s_dys[o0 + 0] + s_dyb[o0 + 0] + s_lep[pp * 68 + o0 + 0];
        out[base + 1 * NH * NW] = a1 * s_dys[o0 + 1] + s_dyb[o0 + 1] + s_lep[pp * 68 + o0 + 1];
        out[base + 2 * NH * NW] = a2 * s_dys[o0 + 2] + s_dyb[o0 + 2] + s_lep[pp * 68 + o0 + 2];
        out[base + 3 * NH * NW] = a3 * s_dys[o0 + 3] + s_dyb[o0 + 3] + s_lep[pp * 68 + o0 + 3];
    }
}

extern "C" void kernel_launch(void* const* d_in, const int* in_sizes, int n_in,
                              void* d_out, int out_size) {
    const float* x       = (const float*)d_in[0];
    const float* lepe_w  = (const float*)d_in[1];
    const float* lepe_b  = (const float*)d_in[2];
    const float* lepe_s  = (const float*)d_in[3];
    const float* lepe_bb = (const float*)d_in[4];
    const float* wq_w    = (const float*)d_in[5];
    const float* wq_s    = (const float*)d_in[6];
    const float* wq_b    = (const float*)d_in[7];
    const float* wk_w    = (const float*)d_in[8];
    const float* wk_s    = (const float*)d_in[9];
    const float* wk_b    = (const float*)d_in[10];
    const float* wp_w    = (const float*)d_in[11];
    const float* wp_b    = (const float*)d_in[12];
    const float* rpb1    = (const float*)d_in[13];
    const float* rpb2    = (const float*)d_in[14];
    const float* dy_w    = (const float*)d_in[15];
    const float* dy_s    = (const float*)d_in[16];
    const float* dy_b    = (const float*)d_in[17];
    float* out = (float*)d_out;

    float* kgp = nullptr;
    cudaGetSymbolAddress((void**)&kgp, g_kg);

    cudaFuncSetAttribute(k_main, cudaFuncAttributeMaxDynamicSharedMemorySize, SMEM_BYTES);

    k_pool<<<dim3(7, NB), 256>>>(x, wk_w, wk_s, wk_b, kgp);
    k_main<<<dim3(NH, NB), 256, SMEM_BYTES>>>(
        x, lepe_w, lepe_b, lepe_s, lepe_bb,
        wq_w, wq_s, wq_b, wp_w, wp_b,
        rpb1, rpb2, dy_w, dy_s, dy_b, kgp, out);
}

// round 8
// speedup vs baseline: 2.8447x; 1.3326x over previous
#include <cuda_runtime.h>

// ContMix fused, fp32 + f32x2 FMA, attn-in-registers, pipelined P5,
// WK-factored attention logits (K=49 -> K=8 via per-batch precompute).
// B=32, C=64, H=W=56, G=4, C2=32, SMK=5, K=7, SCALE=0.25

#define NB 32
#define NC 64
#define NH 56
#define NW 56

__device__ float g_kg[NB * 32 * 49];
__device__ float g_wk[NB * 32 * 80];   // WK[b][g*8+c][m(padded 80)]

// Smem layout (float offsets; float4 regions 16B-aligned)
#define O_WQT   0        // 1024  wqT[i*32+o] (scale-folded)
#define O_QB    1024     // 32    0.25*wq_b
#define O_WPB   1056     // 80 (padded)
#define O_WK    1136     // 32*80 = 2560
#define O_DYW   3696     // 4096
#define O_DYS   7792     // 64
#define O_DYB   7856     // 64
#define O_LEPW  7920     // 3136
#define O_LSC   11056    // 64
#define O_LOF   11120    // 64
#define O_RPB1  11184    // 324
#define O_RPB2  11508    // 676
#define O_M     12184    // 56*68 = 3808 (union: xrow 1792 in P0/P3, m in P5/P6)
#define O_LEP   15992    // 3808
#define O_XCH   19800    // 2 buffers x 1792 = 3584
#define SMEM_FLOATS 23384
#define SMEM_BYTES (SMEM_FLOATS * 4)

// clamp helper matching numpy repeat-based bias index construction
__device__ __forceinline__ int bcl(int r, int kh, int k) {
    return r < kh ? r : (r >= 56 - kh ? (k - 1) - (55 - r) : kh);
}

__global__ void k_pool(const float* __restrict__ x,
                       const float* __restrict__ wk_w,
                       const float* __restrict__ wk_s,
                       const float* __restrict__ wk_b,
                       float* __restrict__ kg) {
    const int s = blockIdx.x;      // l-slice 0..6
    const int b = blockIdx.y;
    const int tid = threadIdx.x;
    const int l0 = s * 7;
    __shared__ float s_pool[32 * 7];
    __shared__ float s_wk[32 * 32];
    for (int t = tid; t < 1024; t += 256) s_wk[t] = wk_w[t];
    if (tid < 224) {
        int ic = tid / 7, lj = tid % 7;
        int l = l0 + lj;
        int i = l / 7, j = l % 7;
        const float* base = x + (((size_t)b * NC + 32 + ic) * NH + i * 8) * NW + j * 8;
        float sum = 0.f;
        #pragma unroll
        for (int y = 0; y < 8; y++) {
            #pragma unroll
            for (int xx = 0; xx < 8; xx++) sum += base[y * NW + xx];
        }
        s_pool[ic * 7 + lj] = sum * (1.0f / 64.0f);
    }
    __syncthreads();
    if (tid < 224) {
        int oc = tid / 7, lj = tid % 7;
        float acc = 0.f;
        #pragma unroll
        for (int ic = 0; ic < 32; ic++)
            acc += s_wk[oc * 32 + ic] * s_pool[ic * 7 + lj];
        kg[(size_t)b * 1568 + oc * 49 + l0 + lj] = acc * wk_s[oc] + wk_b[oc];
    }
}

// WK[b][chan][m] = sum_l wp_w[m*49+l] * kg[b][chan*49+l]   (m padded to 80)
__global__ void k_wk(const float* __restrict__ wp_w,
                     const float* __restrict__ kg,
                     float* __restrict__ wk) {
    const int b = blockIdx.x;
    const int tid = threadIdx.x;
    __shared__ float s_kg[1568];
    __shared__ float s_wp[3626];
    for (int t = tid; t < 1568; t += 256) s_kg[t] = kg[(size_t)b * 1568 + t];
    for (int t = tid; t < 3626; t += 256) s_wp[t] = wp_w[t];
    __syncthreads();
    for (int t = tid; t < 2560; t += 256) {
        int chan = t / 80, m = t % 80;
        float acc = 0.f;
        if (m < 74) {
            const float* wr = s_wp + m * 49;
            const float* kr = s_kg + chan * 49;
            #pragma unroll
            for (int l = 0; l < 49; l++) acc += wr[l] * kr[l];
        }
        wk[(size_t)b * 2560 + t] = acc;
    }
}

__global__ __launch_bounds__(256, 2)
void k_main(const float* __restrict__ x,
            const float* __restrict__ lepe_w, const float* __restrict__ lepe_b,
            const float* __restrict__ lepe_s, const float* __restrict__ lepe_bb,
            const float* __restrict__ wq_w, const float* __restrict__ wq_s,
            const float* __restrict__ wq_b,
            const float* __restrict__ wp_b,
            const float* __restrict__ rpb1, const float* __restrict__ rpb2,
            const float* __restrict__ dy_w, const float* __restrict__ dy_s,
            const float* __restrict__ dy_b,
            const float* __restrict__ wkmat,
            float* __restrict__ out) {
    extern __shared__ float sm[];
    const int h = blockIdx.x;
    const int b = blockIdx.y;
    const int tid = threadIdx.x;

    float* s_wqT  = sm + O_WQT;
    float* s_qb   = sm + O_QB;
    float* s_wpb  = sm + O_WPB;
    float* s_wk   = sm + O_WK;
    float* s_dyw  = sm + O_DYW;
    float* s_dys  = sm + O_DYS;
    float* s_dyb  = sm + O_DYB;
    float* s_lepw = sm + O_LEPW;
    float* s_lsc  = sm + O_LSC;
    float* s_lof  = sm + O_LOF;
    float* s_rpb1 = sm + O_RPB1;
    float* s_rpb2 = sm + O_RPB2;
    float* s_lep  = sm + O_LEP;

    // ---- P0: stage weights ----
    for (int t = tid; t < 1024; t += 256) {
        int i = t >> 5, o = t & 31;
        s_wqT[t] = wq_w[o * 32 + i] * 0.25f * wq_s[o];
    }
    if (tid < 32) s_qb[tid] = 0.25f * wq_b[tid];
    if (tid < 80) s_wpb[tid] = (tid < 74) ? wp_b[tid] : 0.f;
    for (int t = tid; t < 2560; t += 256) s_wk[t] = wkmat[(size_t)b * 2560 + t];
    for (int t = tid; t < 4096; t += 256) s_dyw[t] = dy_w[t];
    if (tid < 64) {
        s_dys[tid] = dy_s[tid];
        s_dyb[tid] = dy_b[tid];
        float s = lepe_s[tid];
        s_lsc[tid] = s;
        s_lof[tid] = lepe_b[tid] * s + lepe_bb[tid];
    }
    for (int t = tid; t < 3136; t += 256) s_lepw[t] = lepe_w[t];
    for (int t = tid; t < 324; t += 256) s_rpb1[t] = rpb1[t];
    for (int t = tid; t < 676; t += 256) s_rpb2[t] = rpb2[t];

    // xrow: first 32 channels of this row, into the union buffer (O_M)
    float* s_xrow = sm + O_M;
    for (int t = tid; t < 1792; t += 256) {
        int i = t / 56, p = t % 56;
        s_xrow[t] = x[(((size_t)b * NC + i) * NH + h) * NW + p];
    }
    __syncthreads();

    const int p = tid % 56;
    const int g = tid / 56;   // valid when tid < 224

    // ---- P3: q-proj (regs) + WK-GEMM (K=8, f32x2) + rpb + dual softmax;
    //      attn stays in registers through P5 ----
    float attn[74];
    if (tid < 224) {
        float qr[8];
        #pragma unroll
        for (int c = 0; c < 8; c++) qr[c] = s_qb[g * 8 + c];
        #pragma unroll
        for (int i = 0; i < 32; i++) {
            float xv = s_xrow[i * 56 + p];
            const float4* w = (const float4*)(s_wqT + i * 32 + g * 8);
            float4 w0 = w[0], w1 = w[1];
            qr[0] += w0.x * xv; qr[1] += w0.y * xv; qr[2] += w0.z * xv; qr[3] += w0.w * xv;
            qr[4] += w1.x * xv; qr[5] += w1.y * xv; qr[6] += w1.z * xv; qr[7] += w1.w * xv;
        }

        #pragma unroll
        for (int half = 0; half < 2; half++) {
            const int M0 = half * 40;
            unsigned long long acc2[20];
            #pragma unroll
            for (int mm = 0; mm < 20; mm++) {
                float b0 = s_wpb[M0 + 2 * mm], b1 = s_wpb[M0 + 2 * mm + 1];
                asm("mov.b64 %0, {%1, %2};" : "=l"(acc2[mm]) : "f"(b0), "f"(b1));
            }
            #pragma unroll
            for (int c = 0; c < 8; c++) {
                unsigned long long vv;
                asm("mov.b64 %0, {%1, %1};" : "=l"(vv) : "f"(qr[c]));
                const ulonglong2* w2 = (const ulonglong2*)(s_wk + (g * 8 + c) * 80 + M0);
                #pragma unroll
                for (int mm = 0; mm < 10; mm++) {
                    ulonglong2 w = w2[mm];
                    asm("fma.rn.f32x2 %0, %1, %2, %0;" : "+l"(acc2[2 * mm])     : "l"(w.x), "l"(vv));
                    asm("fma.rn.f32x2 %0, %1, %2, %0;" : "+l"(acc2[2 * mm + 1]) : "l"(w.y), "l"(vv));
                }
            }
            #pragma unroll
            for (int mm = 0; mm < 20; mm++) {
                float f0, f1;
                asm("mov.b64 {%0, %1}, %2;" : "=f"(f0), "=f"(f1) : "l"(acc2[mm]));
                int idx = M0 + 2 * mm;
                if (idx < 74)     attn[idx] = f0;
                if (idx + 1 < 74) attn[idx + 1] = f1;
            }
        }

        // relative position bias (derived from numpy _bias_idx incl. [::-1])
        int bh5 = bcl(55 - h, 2, 5), bw5 = bcl(55 - p, 2, 5);
        int bh7 = bcl(55 - h, 3, 7), bw7 = bcl(55 - p, 3, 7);
        const float* r1 = s_rpb1 + g * 81;
        const float* r2 = s_rpb2 + g * 169;
        #pragma unroll
        for (int m = 0; m < 25; m++) {
            int dh = m / 5, dw = m % 5;
            attn[m] += r1[(bh5 + dh) * 9 + bw5 + dw];
        }
        #pragma unroll
        for (int j = 0; j < 49; j++) {
            int dh = j / 7, dw = j % 7;
            attn[25 + j] += r2[(bh7 + dh) * 13 + bw7 + dw];
        }
        // softmax over taps [0,25)
        {
            float mx = -1e30f;
            #pragma unroll
            for (int m = 0; m < 25; m++) mx = fmaxf(mx, attn[m]);
            float s = 0.f;
            #pragma unroll
            for (int m = 0; m < 25; m++) { attn[m] = __expf(attn[m] - mx); s += attn[m]; }
            float inv = 1.0f / s;
            #pragma unroll
            for (int m = 0; m < 25; m++) attn[m] *= inv;
        }
        // softmax over taps [25,74)
        {
            float mx = -1e30f;
            #pragma unroll
            for (int m = 25; m < 74; m++) mx = fmaxf(mx, attn[m]);
            float s = 0.f;
            #pragma unroll
            for (int m = 25; m < 74; m++) { attn[m] = __expf(attn[m] - mx); s += attn[m]; }
            float inv = 1.0f / s;
            #pragma unroll
            for (int m = 25; m < 74; m++) attn[m] *= inv;
        }
    }

    // ---- P5: pipelined lepe + dynamic mixing; 16 sub-chunks of 4 channels,
    // double-buffered in xch. Division-free staging map.
    float* s_m = sm + O_M;
    const int slot = tid >> 6;
    const int wi = tid & 63;
    const bool vw = (wi >= 3) && (wi <= 58);
    const int gw = wi - 3;

    // prologue: stage sub-chunk 0 into buffer 0
    {
        const float* src = x + ((size_t)b * NC + slot * 8) * (NH * NW);
        float* dst = sm + O_XCH + slot * 448 + wi;
        #pragma unroll
        for (int rr = 0; rr < 7; rr++) {
            int gy = h - 3 + rr;
            float v = (vw && (unsigned)gy < 56u) ? src[gy * NW + gw] : 0.f;
            dst[rr * 64] = v;
        }
    }
    __syncthreads();   // also guarantees all P3 xrow reads done before s_m writes

    for (int sc = 0; sc < 16; sc++) {
        float nx[7];
        if (sc < 15) {
            int s1 = sc + 1;
            int ch = ((s1 >> 3) << 5) + slot * 8 + (s1 & 7);
            const float* src = x + ((size_t)b * NC + ch) * (NH * NW);
            #pragma unroll
            for (int rr = 0; rr < 7; rr++) {
                int gy = h - 3 + rr;
                nx[rr] = (vw && (unsigned)gy < 56u) ? src[gy * NW + gw] : 0.f;
            }
        }
        if (tid < 224) {
            const float* xb = sm + O_XCH + (sc & 1) * 1792 + g * 448 + p;
            int ccc = sc & 7;
            if (sc < 8) {
                int ch = g * 8 + ccc;
                const float* lw = s_lepw + ch * 49;
                float lac = 0.f, mac = 0.f;
                #pragma unroll
                for (int dh = 0; dh < 7; dh++) {
                    #pragma unroll
                    for (int dw = 0; dw < 7; dw++) {
                        float xv = xb[dh * 64 + dw];
                        lac += lw[dh * 7 + dw] * xv;
                        if (dh >= 1 && dh <= 5 && dw >= 1 && dw <= 5)
                            mac += attn[(dh - 1) * 5 + (dw - 1)] * xv;
                    }
                }
                s_m[p * 68 + ch] = mac;
                s_lep[p * 68 + ch] = lac * s_lsc[ch] + s_lof[ch];
            } else {
                int ch = 32 + g * 8 + ccc;
                const float* lw = s_lepw + ch * 49;
                float lac = 0.f, mac = 0.f;
                #pragma unroll
                for (int dh = 0; dh < 7; dh++) {
                    #pragma unroll
                    for (int dw = 0; dw < 7; dw++) {
                        float xv = xb[dh * 64 + dw];
                        lac += lw[dh * 7 + dw] * xv;
                        mac += attn[25 + dh * 7 + dw] * xv;
                    }
                }
                s_m[p * 68 + ch] = mac;
                s_lep[p * 68 + ch] = lac * s_lsc[ch] + s_lof[ch];
            }
        }
        if (sc < 15) {
            float* dst = sm + O_XCH + ((sc + 1) & 1) * 1792 + slot * 448 + wi;
            #pragma unroll
            for (int rr = 0; rr < 7; rr++) dst[rr * 64] = nx[rr];
        }
        __syncthreads();
    }

    // ---- P6: dy 64x64 GEMM (float4) + bn + lepe ----
    for (int t = tid; t < 896; t += 256) {
        int og = t / 56, pp = t % 56;
        int o0 = og * 4;
        const float4* m4 = (const float4*)(s_m + pp * 68);
        const float4* w0 = (const float4*)(s_dyw + (o0 + 0) * 64);
        const float4* w1 = (const float4*)(s_dyw + (o0 + 1) * 64);
        const float4* w2 = (const float4*)(s_dyw + (o0 + 2) * 64);
        const float4* w3 = (const float4*)(s_dyw + (o0 + 3) * 64);
        float a0 = 0.f, a1 = 0.f, a2 = 0.f, a3 = 0.f;
        #pragma unroll
        for (int i = 0; i < 16; i++) {
            float4 mv = m4[i];
            float4 v0 = w0[i], v1 = w1[i], v2 = w2[i], v3 = w3[i];
            a0 += v0.x * mv.x + v0.y * mv.y + v0.z * mv.z + v0.w * mv.w;
            a1 += v1.x * mv.x + v1.y * mv.y + v1.z * mv.z + v1.w * mv.w;
            a2 += v2.x * mv.x + v2.y * mv.y + v2.z * mv.z + v2.w * mv.w;
            a3 += v3.x * mv.x + v3.y * mv.y + v3.z * mv.z + v3.w * mv.w;
        }
        size_t base = (((size_t)b * NC + o0) * NH + h) * NW + pp;
        out[base + 0 * NH * NW] = a0 * s_dys[o0 + 0] + s_dyb[o0 + 0] + s_lep[pp * 68 + o0 + 0];
        out[base + 1 * NH * NW] = a1 * s_dys[o0 + 1] + s_dyb[o0 + 1] + s_lep[pp * 68 + o0 + 1];
        out[base + 2 * NH * NW] = a2 * s_dys[o0 + 2] + s_dyb[o0 + 2] + s_lep[pp * 68 + o0 + 2];
        out[base + 3 * NH * NW] = a3 * s_dys[o0 + 3] + s_dyb[o0 + 3] + s_lep[pp * 68 + o0 + 3];
    }
}

extern "C" void kernel_launch(void* const* d_in, const int* in_sizes, int n_in,
                              void* d_out, int out_size) {
    const float* x       = (const float*)d_in[0];
    const float* lepe_w  = (const float*)d_in[1];
    const float* lepe_b  = (const float*)d_in[2];
    const float* lepe_s  = (const float*)d_in[3];
    const float* lepe_bb = (const float*)d_in[4];
    const float* wq_w    = (const float*)d_in[5];
    const float* wq_s    = (const float*)d_in[6];
    const float* wq_b    = (const float*)d_in[7];
    const float* wk_w    = (const float*)d_in[8];
    const float* wk_s    = (const float*)d_in[9];
    const float* wk_b    = (const float*)d_in[10];
    const float* wp_w    = (const float*)d_in[11];
    const float* wp_b    = (const float*)d_in[12];
    const float* rpb1    = (const float*)d_in[13];
    const float* rpb2    = (const float*)d_in[14];
    const float* dy_w    = (const float*)d_in[15];
    const float* dy_s    = (const float*)d_in[16];
    const float* dy_b    = (const float*)d_in[17];
    float* out = (float*)d_out;

    float* kgp = nullptr;
    cudaGetSymbolAddress((void**)&kgp, g_kg);
    float* wkp = nullptr;
    cudaGetSymbolAddress((void**)&wkp, g_wk);

    cudaFuncSetAttribute(k_main, cudaFuncAttributeMaxDynamicSharedMemorySize, SMEM_BYTES);

    k_pool<<<dim3(7, NB), 256>>>(x, wk_w, wk_s, wk_b, kgp);
    k_wk<<<NB, 256>>>(wp_w, kgp, wkp);
    k_main<<<dim3(NH, NB), 256, SMEM_BYTES>>>(
        x, lepe_w, lepe_b, lepe_s, lepe_bb,
        wq_w, wq_s, wq_b, wp_b,
        rpb1, rpb2, dy_w, dy_s, dy_b, wkp, out);
}

// round 9
// speedup vs baseline: 2.9945x; 1.0527x over previous
#include <cuda_runtime.h>

// ContMix fused, fp32 + f32x2 FMA, attn-in-registers, pipelined P5,
// WK-factored logits, standalone lepe kernel.
// B=32, C=64, H=W=56, G=4, C2=32, SMK=5, K=7, SCALE=0.25

#define NB 32
#define NC 64
#define NH 56
#define NW 56

__device__ float g_kg[NB * 32 * 49];
__device__ float g_wk[NB * 32 * 80];            // WK[b][g*8+c][m(padded 80)]
__device__ float g_lep[NB * NC * NH * NW];      // lepe+bn output

// Smem layout for k_main (float offsets; float4 regions 16B-aligned)
#define O_WQT   0        // 1024  wqT[i*32+o] (scale-folded)
#define O_QB    1024     // 32    0.25*wq_b
#define O_WPB   1056     // 80 (padded)
#define O_WK    1136     // 32*80 = 2560
#define O_DYW   3696     // 4096
#define O_DYS   7792     // 64
#define O_DYB   7856     // 64
#define O_RPB1  7920     // 324
#define O_RPB2  8244     // 676
#define O_M     8920     // 56*68 = 3808 (union: xrow 1792 in P0/P3, m in P5/P6)
#define O_XCH   12728    // 2 buffers x 1792 = 3584
#define SMEM_FLOATS 16312
#define SMEM_BYTES (SMEM_FLOATS * 4)

// clamp helper matching numpy repeat-based bias index construction
__device__ __forceinline__ int bcl(int r, int kh, int k) {
    return r < kh ? r : (r >= 56 - kh ? (k - 1) - (55 - r) : kh);
}

__global__ void k_pool(const float* __restrict__ x,
                       const float* __restrict__ wk_w,
                       const float* __restrict__ wk_s,
                       const float* __restrict__ wk_b,
                       float* __restrict__ kg) {
    const int s = blockIdx.x;      // l-slice 0..6
    const int b = blockIdx.y;
    const int tid = threadIdx.x;
    const int l0 = s * 7;
    __shared__ float s_pool[32 * 7];
    __shared__ float s_wk[32 * 32];
    for (int t = tid; t < 1024; t += 256) s_wk[t] = wk_w[t];
    if (tid < 224) {
        int ic = tid / 7, lj = tid % 7;
        int l = l0 + lj;
        int i = l / 7, j = l % 7;
        const float4* base = (const float4*)(x + (((size_t)b * NC + 32 + ic) * NH + i * 8) * NW + j * 8);
        float sum = 0.f;
        #pragma unroll
        for (int y = 0; y < 8; y++) {
            float4 a = base[y * 14];
            float4 c = base[y * 14 + 1];
            sum += a.x + a.y + a.z + a.w + c.x + c.y + c.z + c.w;
        }
        s_pool[ic * 7 + lj] = sum * (1.0f / 64.0f);
    }
    __syncthreads();
    if (tid < 224) {
        int oc = tid / 7, lj = tid % 7;
        float acc = 0.f;
        #pragma unroll
        for (int ic = 0; ic < 32; ic++)
            acc += s_wk[oc * 32 + ic] * s_pool[ic * 7 + lj];
        kg[(size_t)b * 1568 + oc * 49 + l0 + lj] = acc * wk_s[oc] + wk_b[oc];
    }
}

// WK[b][chan][m] = sum_l wp_w[m*49+l] * kg[b][chan*49+l]   (m padded to 80)
__global__ void k_wk(const float* __restrict__ wp_w,
                     const float* __restrict__ kg,
                     float* __restrict__ wk) {
    const int b = blockIdx.x;
    const int tid = threadIdx.x;
    __shared__ float s_kg[1568];
    __shared__ float s_wp[3626];
    for (int t = tid; t < 1568; t += 256) s_kg[t] = kg[(size_t)b * 1568 + t];
    for (int t = tid; t < 3626; t += 256) s_wp[t] = wp_w[t];
    __syncthreads();
    for (int t = tid; t < 2560; t += 256) {
        int chan = t / 80, m = t % 80;
        float acc = 0.f;
        if (m < 74) {
            const float* wr = s_wp + m * 49;
            const float* kr = s_kg + chan * 49;
            #pragma unroll
            for (int l = 0; l < 49; l++) acc += wr[l] * kr[l];
        }
        wk[(size_t)b * 2560 + t] = acc;
    }
}

// Depthwise 7x7 lepe conv + bn -> g_lep. Block per (c, b); sliding-window
// strips of 14 outputs per thread (weights from smem rows into regs).
__global__ __launch_bounds__(256, 3)
void k_lepe(const float* __restrict__ x,
            const float* __restrict__ lepe_w, const float* __restrict__ lepe_b,
            const float* __restrict__ lepe_s, const float* __restrict__ lepe_bb,
            float* __restrict__ lep) {
    const int c = blockIdx.x;
    const int b = blockIdx.y;
    const int tid = threadIdx.x;
    __shared__ float tile[62 * 64];
    __shared__ float s_lw[49];
    const float* src = x + ((size_t)b * NC + c) * (NH * NW);
    for (int t = tid; t < 62 * 64; t += 256) {
        int r = t >> 6, w = t & 63;
        int gy = r - 3, gx = w - 3;
        float v = 0.f;
        if ((unsigned)gy < 56u && (unsigned)gx < 56u) v = src[gy * 56 + gx];
        tile[t] = v;
    }
    if (tid < 49) s_lw[tid] = lepe_w[c * 49 + tid];
    __syncthreads();
    if (tid < 224) {
        const float scl = lepe_s[c];
        const float off = lepe_b[c] * scl + lepe_bb[c];
        const int r = tid >> 2;
        const int w0 = (tid & 3) * 14;
        float acc[14];
        #pragma unroll
        for (int k = 0; k < 14; k++) acc[k] = 0.f;
        #pragma unroll
        for (int dh = 0; dh < 7; dh++) {
            const float* trow = tile + (r + dh) * 64 + w0;
            float win[20];
            #pragma unroll
            for (int j = 0; j < 20; j++) win[j] = trow[j];
            float lw[7];
            #pragma unroll
            for (int j = 0; j < 7; j++) lw[j] = s_lw[dh * 7 + j];
            #pragma unroll
            for (int k = 0; k < 14; k++) {
                #pragma unroll
                for (int dw = 0; dw < 7; dw++) acc[k] += lw[dw] * win[k + dw];
            }
        }
        float* dst = lep + ((size_t)b * NC + c) * (NH * NW) + r * 56 + w0;
        #pragma unroll
        for (int k = 0; k < 14; k++) dst[k] = acc[k] * scl + off;
    }
}

__global__ __launch_bounds__(256, 2)
void k_main(const float* __restrict__ x,
            const float* __restrict__ wq_w, const float* __restrict__ wq_s,
            const float* __restrict__ wq_b,
            const float* __restrict__ wp_b,
            const float* __restrict__ rpb1, const float* __restrict__ rpb2,
            const float* __restrict__ dy_w, const float* __restrict__ dy_s,
            const float* __restrict__ dy_b,
            const float* __restrict__ wkmat,
            const float* __restrict__ lep,
            float* __restrict__ out) {
    extern __shared__ float sm[];
    const int h = blockIdx.x;
    const int b = blockIdx.y;
    const int tid = threadIdx.x;

    float* s_wqT  = sm + O_WQT;
    float* s_qb   = sm + O_QB;
    float* s_wpb  = sm + O_WPB;
    float* s_wk   = sm + O_WK;
    float* s_dyw  = sm + O_DYW;
    float* s_dys  = sm + O_DYS;
    float* s_dyb  = sm + O_DYB;
    float* s_rpb1 = sm + O_RPB1;
    float* s_rpb2 = sm + O_RPB2;

    // ---- P0: stage weights ----
    for (int t = tid; t < 1024; t += 256) {
        int i = t >> 5, o = t & 31;
        s_wqT[t] = wq_w[o * 32 + i] * 0.25f * wq_s[o];
    }
    if (tid < 32) s_qb[tid] = 0.25f * wq_b[tid];
    if (tid < 80) s_wpb[tid] = (tid < 74) ? wp_b[tid] : 0.f;
    for (int t = tid; t < 2560; t += 256) s_wk[t] = wkmat[(size_t)b * 2560 + t];
    for (int t = tid; t < 4096; t += 256) s_dyw[t] = dy_w[t];
    if (tid < 64) { s_dys[tid] = dy_s[tid]; s_dyb[tid] = dy_b[tid]; }
    for (int t = tid; t < 324; t += 256) s_rpb1[t] = rpb1[t];
    for (int t = tid; t < 676; t += 256) s_rpb2[t] = rpb2[t];

    // xrow: first 32 channels of this row, into the union buffer (O_M)
    float* s_xrow = sm + O_M;
    for (int t = tid; t < 1792; t += 256) {
        int i = t / 56, p = t % 56;
        s_xrow[t] = x[(((size_t)b * NC + i) * NH + h) * NW + p];
    }
    __syncthreads();

    const int p = tid % 56;
    const int g = tid / 56;   // valid when tid < 224

    // ---- P3: q-proj (regs) + WK-GEMM (K=8, f32x2) + rpb + dual softmax ----
    float attn[74];
    if (tid < 224) {
        float qr[8];
        #pragma unroll
        for (int c = 0; c < 8; c++) qr[c] = s_qb[g * 8 + c];
        #pragma unroll
        for (int i = 0; i < 32; i++) {
            float xv = s_xrow[i * 56 + p];
            const float4* w = (const float4*)(s_wqT + i * 32 + g * 8);
            float4 w0 = w[0], w1 = w[1];
            qr[0] += w0.x * xv; qr[1] += w0.y * xv; qr[2] += w0.z * xv; qr[3] += w0.w * xv;
            qr[4] += w1.x * xv; qr[5] += w1.y * xv; qr[6] += w1.z * xv; qr[7] += w1.w * xv;
        }

        #pragma unroll
        for (int half = 0; half < 2; half++) {
            const int M0 = half * 40;
            unsigned long long acc2[20];
            #pragma unroll
            for (int mm = 0; mm < 20; mm++) {
                float b0 = s_wpb[M0 + 2 * mm], b1 = s_wpb[M0 + 2 * mm + 1];
                asm("mov.b64 %0, {%1, %2};" : "=l"(acc2[mm]) : "f"(b0), "f"(b1));
            }
            #pragma unroll
            for (int c = 0; c < 8; c++) {
                unsigned long long vv;
                asm("mov.b64 %0, {%1, %1};" : "=l"(vv) : "f"(qr[c]));
                const ulonglong2* w2 = (const ulonglong2*)(s_wk + (g * 8 + c) * 80 + M0);
                #pragma unroll
                for (int mm = 0; mm < 10; mm++) {
                    ulonglong2 w = w2[mm];
                    asm("fma.rn.f32x2 %0, %1, %2, %0;" : "+l"(acc2[2 * mm])     : "l"(w.x), "l"(vv));
                    asm("fma.rn.f32x2 %0, %1, %2, %0;" : "+l"(acc2[2 * mm + 1]) : "l"(w.y), "l"(vv));
                }
            }
            #pragma unroll
            for (int mm = 0; mm < 20; mm++) {
                float f0, f1;
                asm("mov.b64 {%0, %1}, %2;" : "=f"(f0), "=f"(f1) : "l"(acc2[mm]));
                int idx = M0 + 2 * mm;
                if (idx < 74)     attn[idx] = f0;
                if (idx + 1 < 74) attn[idx + 1] = f1;
            }
        }

        // relative position bias (derived from numpy _bias_idx incl. [::-1])
        int bh5 = bcl(55 - h, 2, 5), bw5 = bcl(55 - p, 2, 5);
        int bh7 = bcl(55 - h, 3, 7), bw7 = bcl(55 - p, 3, 7);
        const float* r1 = s_rpb1 + g * 81;
        const float* r2 = s_rpb2 + g * 169;
        #pragma unroll
        for (int m = 0; m < 25; m++) {
            int dh = m / 5, dw = m % 5;
            attn[m] += r1[(bh5 + dh) * 9 + bw5 + dw];
        }
        #pragma unroll
        for (int j = 0; j < 49; j++) {
            int dh = j / 7, dw = j % 7;
            attn[25 + j] += r2[(bh7 + dh) * 13 + bw7 + dw];
        }
        // softmax over taps [0,25)
        {
            float mx = -1e30f;
            #pragma unroll
            for (int m = 0; m < 25; m++) mx = fmaxf(mx, attn[m]);
            float s = 0.f;
            #pragma unroll
            for (int m = 0; m < 25; m++) { attn[m] = __expf(attn[m] - mx); s += attn[m]; }
            float inv = 1.0f / s;
            #pragma unroll
            for (int m = 0; m < 25; m++) attn[m] *= inv;
        }
        // softmax over taps [25,74)
        {
            float mx = -1e30f;
            #pragma unroll
            for (int m = 25; m < 74; m++) mx = fmaxf(mx, attn[m]);
            float s = 0.f;
            #pragma unroll
            for (int m = 25; m < 74; m++) { attn[m] = __expf(attn[m] - mx); s += attn[m]; }
            float inv = 1.0f / s;
            #pragma unroll
            for (int m = 25; m < 74; m++) attn[m] *= inv;
        }
    }

    // ---- P5: pipelined dynamic mixing only; 16 sub-chunks of 4 channels,
    // double-buffered. 5x5 sub-chunks (sc<8) touch only rows 1..5 / 25 taps.
    float* s_m = sm + O_M;
    const int slot = tid >> 6;
    const int wi = tid & 63;
    const bool vw = (wi >= 3) && (wi <= 58);
    const int gw = wi - 3;

    // prologue: stage sub-chunk 0 (5x5 -> rows 1..5) into buffer 0
    {
        const float* src = x + ((size_t)b * NC + slot * 8) * (NH * NW);
        float* dst = sm + O_XCH + slot * 448 + wi;
        #pragma unroll
        for (int rr = 1; rr <= 5; rr++) {
            int gy = h - 3 + rr;
            float v = (vw && (unsigned)gy < 56u) ? src[gy * NW + gw] : 0.f;
            dst[rr * 64] = v;
        }
    }
    __syncthreads();   // also guarantees all P3 xrow reads done before s_m writes

    for (int sc = 0; sc < 16; sc++) {
        float nx[7];
        const int s1 = sc + 1;
        const bool full = (s1 >= 8);
        if (sc < 15) {
            int ch = ((s1 >> 3) << 5) + slot * 8 + (s1 & 7);
            const float* src = x + ((size_t)b * NC + ch) * (NH * NW);
            #pragma unroll
            for (int rr = 0; rr < 7; rr++) {
                if (full || (rr >= 1 && rr <= 5)) {
                    int gy = h - 3 + rr;
                    nx[rr] = (vw && (unsigned)gy < 56u) ? src[gy * NW + gw] : 0.f;
                }
            }
        }
        if (tid < 224) {
            const float* xb = sm + O_XCH + (sc & 1) * 1792 + g * 448 + p;
            int ccc = sc & 7;
            if (sc < 8) {
                int ch = g * 8 + ccc;
                float mac0 = 0.f, mac1 = 0.f;
                #pragma unroll
                for (int dh = 1; dh <= 5; dh++) {
                    #pragma unroll
                    for (int dw = 1; dw <= 5; dw++) {
                        float xv = xb[dh * 64 + dw];
                        if (dw & 1) mac0 += attn[(dh - 1) * 5 + (dw - 1)] * xv;
                        else        mac1 += attn[(dh - 1) * 5 + (dw - 1)] * xv;
                    }
                }
                s_m[p * 68 + ch] = mac0 + mac1;
            } else {
                int ch = 32 + g * 8 + ccc;
                float mac0 = 0.f, mac1 = 0.f;
                #pragma unroll
                for (int dh = 0; dh < 7; dh++) {
                    #pragma unroll
                    for (int dw = 0; dw < 7; dw++) {
                        float xv = xb[dh * 64 + dw];
                        if (dw & 1) mac0 += attn[25 + dh * 7 + dw] * xv;
                        else        mac1 += attn[25 + dh * 7 + dw] * xv;
                    }
                }
                s_m[p * 68 + ch] = mac0 + mac1;
            }
        }
        if (sc < 15) {
            float* dst = sm + O_XCH + (s1 & 1) * 1792 + slot * 448 + wi;
            #pragma unroll
            for (int rr = 0; rr < 7; rr++)
                if (full || (rr >= 1 && rr <= 5)) dst[rr * 64] = nx[rr];
        }
        __syncthreads();
    }

    // ---- P6: dy 64x64 GEMM (float4) + bn + lepe(global) ----
    if (tid < 224) {
        const float* lepb = lep + ((size_t)b * NC) * (NH * NW) + h * NW + p;
        const float4* m4 = (const float4*)(s_m + p * 68);
        #pragma unroll
        for (int k = 0; k < 4; k++) {
            int o0 = (k * 4 + g) * 4;
            float l0 = lepb[(o0 + 0) * 3136];
            float l1 = lepb[(o0 + 1) * 3136];
            float l2 = lepb[(o0 + 2) * 3136];
            float l3 = lepb[(o0 + 3) * 3136];
            const float4* w0 = (const float4*)(s_dyw + (o0 + 0) * 64);
            const float4* w1 = (const float4*)(s_dyw + (o0 + 1) * 64);
            const float4* w2 = (const float4*)(s_dyw + (o0 + 2) * 64);
            const float4* w3 = (const float4*)(s_dyw + (o0 + 3) * 64);
            float a0 = 0.f, a1 = 0.f, a2 = 0.f, a3 = 0.f;
            #pragma unroll
            for (int i = 0; i < 16; i++) {
                float4 mv = m4[i];
                float4 v0 = w0[i], v1 = w1[i], v2 = w2[i], v3 = w3[i];
                a0 += v0.x * mv.x + v0.y * mv.y + v0.z * mv.z + v0.w * mv.w;
                a1 += v1.x * mv.x + v1.y * mv.y + v1.z * mv.z + v1.w * mv.w;
                a2 += v2.x * mv.x + v2.y * mv.y + v2.z * mv.z + v2.w * mv.w;
                a3 += v3.x * mv.x + v3.y * mv.y + v3.z * mv.z + v3.w * mv.w;
            }
            size_t base = (((size_t)b * NC + o0) * NH + h) * NW + p;
            out[base + 0 * 3136] = a0 * s_dys[o0 + 0] + s_dyb[o0 + 0] + l0;
            out[base + 1 * 3136] = a1 * s_dys[o0 + 1] + s_dyb[o0 + 1] + l1;
            out[base + 2 * 3136] = a2 * s_dys[o0 + 2] + s_dyb[o0 + 2] + l2;
            out[base + 3 * 3136] = a3 * s_dys[o0 + 3] + s_dyb[o0 + 3] + l3;
        }
    }
}

extern "C" void kernel_launch(void* const* d_in, const int* in_sizes, int n_in,
                              void* d_out, int out_size) {
    const float* x       = (const float*)d_in[0];
    const float* lepe_w  = (const float*)d_in[1];
    const float* lepe_b  = (const float*)d_in[2];
    const float* lepe_s  = (const float*)d_in[3];
    const float* lepe_bb = (const float*)d_in[4];
    const float* wq_w    = (const float*)d_in[5];
    const float* wq_s    = (const float*)d_in[6];
    const float* wq_b    = (const float*)d_in[7];
    const float* wk_w    = (const float*)d_in[8];
    const float* wk_s    = (const float*)d_in[9];
    const float* wk_b    = (const float*)d_in[10];
    const float* wp_w    = (const float*)d_in[11];
    const float* wp_b    = (const float*)d_in[12];
    const float* rpb1    = (const float*)d_in[13];
    const float* rpb2    = (const float*)d_in[14];
    const float* dy_w    = (const float*)d_in[15];
    const float* dy_s    = (const float*)d_in[16];
    const float* dy_b    = (const float*)d_in[17];
    float* out = (float*)d_out;

    float* kgp = nullptr;
    cudaGetSymbolAddress((void**)&kgp, g_kg);
    float* wkp = nullptr;
    cudaGetSymbolAddress((void**)&wkp, g_wk);
    float* lepp = nullptr;
    cudaGetSymbolAddress((void**)&lepp, g_lep);

    cudaFuncSetAttribute(k_main, cudaFuncAttributeMaxDynamicSharedMemorySize, SMEM_BYTES);

    k_pool<<<dim3(7, NB), 256>>>(x, wk_w, wk_s, wk_b, kgp);
    k_wk<<<NB, 256>>>(wp_w, kgp, wkp);
    k_lepe<<<dim3(NC, NB), 256>>>(x, lepe_w, lepe_b, lepe_s, lepe_bb, lepp);
    k_main<<<dim3(NH, NB), 256, SMEM_BYTES>>>(
        x, wq_w, wq_s, wq_b, wp_b,
        rpb1, rpb2, dy_w, dy_s, dy_b, wkp, lepp, out);
}

// round 12
// speedup vs baseline: 3.2781x; 1.0947x over previous
#include <cuda_runtime.h>

// ContMix fused, fp32 + f32x2 FMA, attn-in-registers, bulk-staged P5 (2 halves),
// WK-factored logits, standalone lepe kernel.
// B=32, C=64, H=W=56, G=4, C2=32, SMK=5, K=7, SCALE=0.25

#define NB 32
#define NC 64
#define NH 56
#define NW 56

__device__ float g_kg[NB * 32 * 49];
__device__ float g_wk[NB * 32 * 80];            // WK[b][g*8+c][m(padded 80)]
__device__ float g_lep[NB * NC * NH * NW];      // lepe+bn output

// Smem layout for k_main (float offsets; float4 regions 16B-aligned)
#define O_WQT   0        // 1024  wqT[i*32+o] (scale-folded)  [unused now, kept name]
#define O_QB    1024     // 32    0.25*wq_b
#define O_WPB   1056     // 80 (padded)
#define O_WK    1136     // 32*80 = 2560
#define O_DYW   3696     // 4096
#define O_DYS   7792     // 64
#define O_DYB   7856     // 64
#define O_RPB1  7920     // 324
#define O_RPB2  8244     // 676
#define O_M     8920     // 56*68 = 3808
#define O_XCH   12728    // 32ch x 7rows x 64 = 14336 halo buffer (one half)
#define SMEM_FLOATS 27064
#define SMEM_BYTES (SMEM_FLOATS * 4)

// clamp helper matching numpy repeat-based bias index construction
__device__ __forceinline__ int bcl(int r, int kh, int k) {
    return r < kh ? r : (r >= 56 - kh ? (k - 1) - (55 - r) : kh);
}

__global__ void k_pool(const float* __restrict__ x,
                       const float* __restrict__ wk_w,
                       const float* __restrict__ wk_s,
                       const float* __restrict__ wk_b,
                       float* __restrict__ kg) {
    const int s = blockIdx.x;      // row-band / l-row 0..6
    const int b = blockIdx.y;
    const int tid = threadIdx.x;
    const int l0 = s * 7;
    __shared__ float s_x[32 * 8 * 56];   // [ic][r][w]
    __shared__ float s_pool[32 * 7];
    __shared__ float s_wk[32 * 32];
    for (int t = tid; t < 1024; t += 256) s_wk[t] = wk_w[t];
    // coalesced float4 staging of x[b, 32.., s*8..s*8+7, :]
    {
        const float4* src = (const float4*)(x + (((size_t)b * NC + 32) * NH + s * 8) * NW);
        float4* dst = (float4*)s_x;
        // channel stride in float4s: 56*56/4 = 784; we need rows s*8..s*8+7 => offset handled above
        for (int t = tid; t < 3584; t += 256) {
            int ic = t / 112, rem = t - ic * 112;   // rem = r*14 + w4
            dst[t] = src[(size_t)ic * 784 + rem];
        }
    }
    __syncthreads();
    if (tid < 224) {
        int ic = tid / 7, lj = tid % 7;
        const float4* base = (const float4*)(s_x + ic * 448 + lj * 8);
        float sum = 0.f;
        #pragma unroll
        for (int y = 0; y < 8; y++) {
            float4 a = base[y * 14];
            float4 c = base[y * 14 + 1];
            sum += a.x + a.y + a.z + a.w + c.x + c.y + c.z + c.w;
        }
        s_pool[ic * 7 + lj] = sum * (1.0f / 64.0f);
    }
    __syncthreads();
    if (tid < 224) {
        int oc = tid / 7, lj = tid % 7;
        float acc = 0.f;
        #pragma unroll
        for (int ic = 0; ic < 32; ic++)
            acc += s_wk[oc * 32 + ic] * s_pool[ic * 7 + lj];
        kg[(size_t)b * 1568 + oc * 49 + l0 + lj] = acc * wk_s[oc] + wk_b[oc];
    }
}

// WK[b][chan][m] = sum_l wp_w[m*49+l] * kg[b][chan*49+l]   (m padded to 80)
__global__ void k_wk(const float* __restrict__ wp_w,
                     const float* __restrict__ kg,
                     float* __restrict__ wk) {
    const int b = blockIdx.x;
    const int tid = threadIdx.x;
    __shared__ float s_kg[1568];
    __shared__ float s_wp[3626];
    for (int t = tid; t < 1568; t += 256) s_kg[t] = kg[(size_t)b * 1568 + t];
    for (int t = tid; t < 3626; t += 256) s_wp[t] = wp_w[t];
    __syncthreads();
    for (int t = tid; t < 2560; t += 256) {
        int chan = t / 80, m = t % 80;
        float acc = 0.f;
        if (m < 74) {
            const float* wr = s_wp + m * 49;
            const float* kr = s_kg + chan * 49;
            #pragma unroll
            for (int l = 0; l < 49; l++) acc += wr[l] * kr[l];
        }
        wk[(size_t)b * 2560 + t] = acc;
    }
}

// Depthwise 7x7 lepe conv + bn -> g_lep. Block per (c, b); sliding-window
// strips of 14 outputs per thread (weights from smem rows into regs).
__global__ __launch_bounds__(256, 3)
void k_lepe(const float* __restrict__ x,
            const float* __restrict__ lepe_w, const float* __restrict__ lepe_b,
            const float* __restrict__ lepe_s, const float* __restrict__ lepe_bb,
            float* __restrict__ lep) {
    const int c = blockIdx.x;
    const int b = blockIdx.y;
    const int tid = threadIdx.x;
    __shared__ float tile[62 * 64];
    __shared__ float s_lw[49];
    const float* src = x + ((size_t)b * NC + c) * (NH * NW);
    for (int t = tid; t < 62 * 64; t += 256) {
        int r = t >> 6, w = t & 63;
        int gy = r - 3, gx = w - 3;
        float v = 0.f;
        if ((unsigned)gy < 56u && (unsigned)gx < 56u) v = src[gy * 56 + gx];
        tile[t] = v;
    }
    if (tid < 49) s_lw[tid] = lepe_w[c * 49 + tid];
    __syncthreads();
    if (tid < 224) {
        const float scl = lepe_s[c];
        const float off = lepe_b[c] * scl + lepe_bb[c];
        const int r = tid >> 2;
        const int w0 = (tid & 3) * 14;
        float acc[14];
        #pragma unroll
        for (int k = 0; k < 14; k++) acc[k] = 0.f;
        #pragma unroll
        for (int dh = 0; dh < 7; dh++) {
            const float* trow = tile + (r + dh) * 64 + w0;
            float win[20];
            #pragma unroll
            for (int j = 0; j < 20; j++) win[j] = trow[j];
            float lw[7];
            #pragma unroll
            for (int j = 0; j < 7; j++) lw[j] = s_lw[dh * 7 + j];
            #pragma unroll
            for (int k = 0; k < 14; k++) {
                #pragma unroll
                for (int dw = 0; dw < 7; dw++) acc[k] += lw[dw] * win[k + dw];
            }
        }
        float* dst = lep + ((size_t)b * NC + c) * (NH * NW) + r * 56 + w0;
        #pragma unroll
        for (int k = 0; k < 14; k++) dst[k] = acc[k] * scl + off;
    }
}

__global__ __launch_bounds__(256, 2)
void k_main(const float* __restrict__ x,
            const float* __restrict__ wq_w, const float* __restrict__ wq_s,
            const float* __restrict__ wq_b,
            const float* __restrict__ wp_b,
            const float* __restrict__ rpb1, const float* __restrict__ rpb2,
            const float* __restrict__ dy_w, const float* __restrict__ dy_s,
            const float* __restrict__ dy_b,
            const float* __restrict__ wkmat,
            const float* __restrict__ lep,
            float* __restrict__ out) {
    extern __shared__ float sm[];
    const int h = blockIdx.x;
    const int b = blockIdx.y;
    const int tid = threadIdx.x;

    float* s_wqT  = sm + O_WQT;
    float* s_qb   = sm + O_QB;
    float* s_wpb  = sm + O_WPB;
    float* s_wk   = sm + O_WK;
    float* s_dyw  = sm + O_DYW;
    float* s_dys  = sm + O_DYS;
    float* s_dyb  = sm + O_DYB;
    float* s_rpb1 = sm + O_RPB1;
    float* s_rpb2 = sm + O_RPB2;
    float* s_m    = sm + O_M;
    float* s_xch  = sm + O_XCH;

    const int warp = tid >> 5;
    const int lane = tid & 31;

    // ---- P0: stage weights + half0 halo (channels 0..31, rows 1..5) ----
    for (int t = tid; t < 1024; t += 256) {
        int i = t >> 5, o = t & 31;
        s_wqT[t] = wq_w[o * 32 + i] * 0.25f * wq_s[o];
    }
    if (tid < 32) s_qb[tid] = 0.25f * wq_b[tid];
    if (tid < 80) s_wpb[tid] = (tid < 74) ? wp_b[tid] : 0.f;
    for (int t = tid; t < 2560; t += 256) s_wk[t] = wkmat[(size_t)b * 2560 + t];
    for (int t = tid; t < 4096; t += 256) s_dyw[t] = dy_w[t];
    if (tid < 64) { s_dys[tid] = dy_s[tid]; s_dyb[tid] = dy_b[tid]; }
    for (int t = tid; t < 324; t += 256) s_rpb1[t] = rpb1[t];
    for (int t = tid; t < 676; t += 256) s_rpb2[t] = rpb2[t];

    // halo staging helper pattern: warp handles 4 channels, lane covers wi and wi+32
    #pragma unroll
    for (int c4 = 0; c4 < 4; c4++) {
        int ch = warp * 4 + c4;
        const float* src = x + ((size_t)b * NC + ch) * (NH * NW);
        #pragma unroll
        for (int rr = 1; rr <= 5; rr++) {
            int gy = h - 3 + rr;
            bool vy = (unsigned)gy < 56u;
            #pragma unroll
            for (int k = 0; k < 2; k++) {
                int wi = lane + k * 32;
                int gx = wi - 3;
                float v = (vy && (unsigned)gx < 56u) ? src[gy * NW + gx] : 0.f;
                s_xch[ch * 448 + rr * 64 + wi] = v;
            }
        }
    }
    __syncthreads();

    const int p = tid % 56;
    const int g = tid / 56;   // valid when tid < 224

    // ---- P3: q-proj (from halo center row) + WK-GEMM (K=8, f32x2) + rpb + softmax ----
    float attn[74];
    if (tid < 224) {
        float qr[8];
        #pragma unroll
        for (int c = 0; c < 8; c++) qr[c] = s_qb[g * 8 + c];
        #pragma unroll
        for (int i = 0; i < 32; i++) {
            float xv = s_xch[i * 448 + 195 + p];   // row rr=3 (center), wi = p+3
            const float4* w = (const float4*)(s_wqT + i * 32 + g * 8);
            float4 w0 = w[0], w1 = w[1];
            qr[0] += w0.x * xv; qr[1] += w0.y * xv; qr[2] += w0.z * xv; qr[3] += w0.w * xv;
            qr[4] += w1.x * xv; qr[5] += w1.y * xv; qr[6] += w1.z * xv; qr[7] += w1.w * xv;
        }

        #pragma unroll
        for (int half = 0; half < 2; half++) {
            const int M0 = half * 40;
            unsigned long long acc2[20];
            #pragma unroll
            for (int mm = 0; mm < 20; mm++) {
                float b0 = s_wpb[M0 + 2 * mm], b1 = s_wpb[M0 + 2 * mm + 1];
                asm("mov.b64 %0, {%1, %2};" : "=l"(acc2[mm]) : "f"(b0), "f"(b1));
            }
            #pragma unroll
            for (int c = 0; c < 8; c++) {
                unsigned long long vv;
                asm("mov.b64 %0, {%1, %1};" : "=l"(vv) : "f"(qr[c]));
                const ulonglong2* w2 = (const ulonglong2*)(s_wk + (g * 8 + c) * 80 + M0);
                #pragma unroll
                for (int mm = 0; mm < 10; mm++) {
                    ulonglong2 w = w2[mm];
                    asm("fma.rn.f32x2 %0, %1, %2, %0;" : "+l"(acc2[2 * mm])     : "l"(w.x), "l"(vv));
                    asm("fma.rn.f32x2 %0, %1, %2, %0;" : "+l"(acc2[2 * mm + 1]) : "l"(w.y), "l"(vv));
                }
            }
            #pragma unroll
            for (int mm = 0; mm < 20; mm++) {
                float f0, f1;
                asm("mov.b64 {%0, %1}, %2;" : "=f"(f0), "=f"(f1) : "l"(acc2[mm]));
                int idx = M0 + 2 * mm;
                if (idx < 74)     attn[idx] = f0;
                if (idx + 1 < 74) attn[idx + 1] = f1;
            }
        }

        // relative position bias (derived from numpy _bias_idx incl. [::-1])
        int bh5 = bcl(55 - h, 2, 5), bw5 = bcl(55 - p, 2, 5);
        int bh7 = bcl(55 - h, 3, 7), bw7 = bcl(55 - p, 3, 7);
        const float* r1 = s_rpb1 + g * 81;
        const float* r2 = s_rpb2 + g * 169;
        #pragma unroll
        for (int m = 0; m < 25; m++) {
            int dh = m / 5, dw = m % 5;
            attn[m] += r1[(bh5 + dh) * 9 + bw5 + dw];
        }
        #pragma unroll
        for (int j = 0; j < 49; j++) {
            int dh = j / 7, dw = j % 7;
            attn[25 + j] += r2[(bh7 + dh) * 13 + bw7 + dw];
        }
        // softmax over taps [0,25)
        {
            float mx = -1e30f;
            #pragma unroll
            for (int m = 0; m < 25; m++) mx = fmaxf(mx, attn[m]);
            float s = 0.f;
            #pragma unroll
            for (int m = 0; m < 25; m++) { attn[m] = __expf(attn[m] - mx); s += attn[m]; }
            float inv = 1.0f / s;
            #pragma unroll
            for (int m = 0; m < 25; m++) attn[m] *= inv;
        }
        // softmax over taps [25,74)
        {
            float mx = -1e30f;
            #pragma unroll
            for (int m = 25; m < 74; m++) mx = fmaxf(mx, attn[m]);
            float s = 0.f;
            #pragma unroll
            for (int m = 25; m < 74; m++) { attn[m] = __expf(attn[m] - mx); s += attn[m]; }
            float inv = 1.0f / s;
            #pragma unroll
            for (int m = 25; m < 74; m++) attn[m] *= inv;
        }

        // ---- P5a: 5x5 mixing for the 8 half-0 channels of group g ----
        #pragma unroll
        for (int j = 0; j < 8; j++) {
            int ch = g * 8 + j;
            const float* xb = s_xch + ch * 448 + p;
            float mac0 = 0.f, mac1 = 0.f;
            #pragma unroll
            for (int dh = 1; dh <= 5; dh++) {
                #pragma unroll
                for (int dw = 1; dw <= 5; dw++) {
                    float xv = xb[dh * 64 + dw];
                    if (dw & 1) mac0 += attn[(dh - 1) * 5 + (dw - 1)] * xv;
                    else        mac1 += attn[(dh - 1) * 5 + (dw - 1)] * xv;
                }
            }
            s_m[p * 68 + ch] = mac0 + mac1;
        }
    }
    __syncthreads();   // all half-0 halo reads done

    // ---- stage half1 halo (channels 32..63, rows 0..6) ----
    #pragma unroll
    for (int c4 = 0; c4 < 4; c4++) {
        int ch = warp * 4 + c4;
        const float* src = x + ((size_t)b * NC + 32 + ch) * (NH * NW);
        #pragma unroll
        for (int rr = 0; rr < 7; rr++) {
            int gy = h - 3 + rr;
            bool vy = (unsigned)gy < 56u;
            #pragma unroll
            for (int k = 0; k < 2; k++) {
                int wi = lane + k * 32;
                int gx = wi - 3;
                float v = (vy && (unsigned)gx < 56u) ? src[gy * NW + gx] : 0.f;
                s_xch[ch * 448 + rr * 64 + wi] = v;
            }
        }
    }
    __syncthreads();

    // ---- P5b: 7x7 mixing for the 8 half-1 channels of group g ----
    if (tid < 224) {
        #pragma unroll
        for (int j = 0; j < 8; j++) {
            int ch = g * 8 + j;           // buffer slot; output channel = 32 + ch
            const float* xb = s_xch + ch * 448 + p;
            float mac0 = 0.f, mac1 = 0.f;
            #pragma unroll
            for (int dh = 0; dh < 7; dh++) {
                #pragma unroll
                for (int dw = 0; dw < 7; dw++) {
                    float xv = xb[dh * 64 + dw];
                    if (dw & 1) mac0 += attn[25 + dh * 7 + dw] * xv;
                    else        mac1 += attn[25 + dh * 7 + dw] * xv;
                }
            }
            s_m[p * 68 + 32 + ch] = mac0 + mac1;
        }
    }
    __syncthreads();

    // ---- P6: dy 64x64 GEMM (float4) + bn + lepe(global) ----
    if (tid < 224) {
        const float* lepb = lep + ((size_t)b * NC) * (NH * NW) + h * NW + p;
        const float4* m4 = (const float4*)(s_m + p * 68);
        #pragma unroll
        for (int k = 0; k < 4; k++) {
            int o0 = (k * 4 + g) * 4;
            float l0 = lepb[(o0 + 0) * 3136];
            float l1 = lepb[(o0 + 1) * 3136];
            float l2 = lepb[(o0 + 2) * 3136];
            float l3 = lepb[(o0 + 3) * 3136];
            const float4* w0 = (const float4*)(s_dyw + (o0 + 0) * 64);
            const float4* w1 = (const float4*)(s_dyw + (o0 + 1) * 64);
            const float4* w2 = (const float4*)(s_dyw + (o0 + 2) * 64);
            const float4* w3 = (const float4*)(s_dyw + (o0 + 3) * 64);
            float a0 = 0.f, a1 = 0.f, a2 = 0.f, a3 = 0.f;
            #pragma unroll
            for (int i = 0; i < 16; i++) {
                float4 mv = m4[i];
                float4 v0 = w0[i], v1 = w1[i], v2 = w2[i], v3 = w3[i];
                a0 += v0.x * mv.x + v0.y * mv.y + v0.z * mv.z + v0.w * mv.w;
                a1 += v1.x * mv.x + v1.y * mv.y + v1.z * mv.z + v1.w * mv.w;
                a2 += v2.x * mv.x + v2.y * mv.y + v2.z * mv.z + v2.w * mv.w;
                a3 += v3.x * mv.x + v3.y * mv.y + v3.z * mv.z + v3.w * mv.w;
            }
            size_t base = (((size_t)b * NC + o0) * NH + h) * NW + p;
            out[base + 0 * 3136] = a0 * s_dys[o0 + 0] + s_dyb[o0 + 0] + l0;
            out[base + 1 * 3136] = a1 * s_dys[o0 + 1] + s_dyb[o0 + 1] + l1;
            out[base + 2 * 3136] = a2 * s_dys[o0 + 2] + s_dyb[o0 + 2] + l2;
            out[base + 3 * 3136] = a3 * s_dys[o0 + 3] + s_dyb[o0 + 3] + l3;
        }
    }
}

extern "C" void kernel_launch(void* const* d_in, const int* in_sizes, int n_in,
                              void* d_out, int out_size) {
    const float* x       = (const float*)d_in[0];
    const float* lepe_w  = (const float*)d_in[1];
    const float* lepe_b  = (const float*)d_in[2];
    const float* lepe_s  = (const float*)d_in[3];
    const float* lepe_bb = (const float*)d_in[4];
    const float* wq_w    = (const float*)d_in[5];
    const float* wq_s    = (const float*)d_in[6];
    const float* wq_b    = (const float*)d_in[7];
    const float* wk_w    = (const float*)d_in[8];
    const float* wk_s    = (const float*)d_in[9];
    const float* wk_b    = (const float*)d_in[10];
    const float* wp_w    = (const float*)d_in[11];
    const float* wp_b    = (const float*)d_in[12];
    const float* rpb1    = (const float*)d_in[13];
    const float* rpb2    = (const float*)d_in[14];
    const float* dy_w    = (const float*)d_in[15];
    const float* dy_s    = (const float*)d_in[16];
    const float* dy_b    = (const float*)d_in[17];
    float* out = (float*)d_out;

    float* kgp = nullptr;
    cudaGetSymbolAddress((void**)&kgp, g_kg);
    float* wkp = nullptr;
    cudaGetSymbolAddress((void**)&wkp, g_wk);
    float* lepp = nullptr;
    cudaGetSymbolAddress((void**)&lepp, g_lep);

    cudaFuncSetAttribute(k_main, cudaFuncAttributeMaxDynamicSharedMemorySize, SMEM_BYTES);

    k_pool<<<dim3(7, NB), 256>>>(x, wk_w, wk_s, wk_b, kgp);
    k_wk<<<NB, 256>>>(wp_w, kgp, wkp);
    k_lepe<<<dim3(NC, NB), 256>>>(x, lepe_w, lepe_b, lepe_s, lepe_bb, lepp);
    k_main<<<dim3(NH, NB), 256, SMEM_BYTES>>>(
        x, wq_w, wq_s, wq_b, wp_b,
        rpb1, rpb2, dy_w, dy_s, dy_b, wkp, lepp, out);
}